// round 1
// baseline (speedup 1.0000x reference)
#include <cuda_runtime.h>
#include <cstdint>

#define S_LEN 4096
#define ROTN  32

// Precomputed combined 64x64 matrix (column-permuted: cols 0..31 = original even
// output cols, 32..63 = original odd output cols), and RoPE sin/cos tables.
__device__ float g_M[64 * 64];
__device__ float g_sin[S_LEN * ROTN];
__device__ float g_cos[S_LEN * ROTN];

// ---------------------------------------------------------------------------
// Precompute M = B_total @ r_matrix (with epilogue column permutation).
// One block, 64 threads; thread t owns row t of the operator.
// ---------------------------------------------------------------------------
__global__ void precomp_M_kernel(const float* __restrict__ thetas,
                                 const float* __restrict__ theta_scale,
                                 const float* __restrict__ rmat,
                                 const int*   __restrict__ pairs) {
    __shared__ float E[64][64];
    int t = threadIdx.x;  // 0..63
    #pragma unroll
    for (int c = 0; c < 64; ++c) E[t][c] = (c == t) ? 1.0f : 0.0f;

    float ts = theta_scale[0];
    for (int s = 0; s < ROTN; ++s) {
        int i = pairs[2 * s], j = pairs[2 * s + 1];
        float th = thetas[s] * ts;                 // fp32 arg, matches reference
        float cth = (float)cos((double)th);        // accurate even w/ fast_math
        float sth = (float)sin((double)th);
        float xi = E[t][i], xj = E[t][j];
        float gi =  xi * cth + xj * sth;
        float gj = -xi * sth + xj * cth;
        float ni = (2.0f * gi + xi - 2.0f * gi * cth) / 3.0f;
        float nj = (2.0f * gj + xj - 2.0f * gi * sth) / 3.0f;  // gi*s, as in ref
        E[t][i] = ni;
        E[t][j] = nj;
    }
    __syncthreads();

    // M[t][c] = sum_k E[t][k] * R[k][perm(c)]
    for (int c = 0; c < 64; ++c) {
        int pc = (c < 32) ? (2 * c) : (2 * (c - 32) + 1);
        float acc = 0.0f;
        for (int k = 0; k < 64; ++k) acc += E[t][k] * rmat[k * 64 + pc];
        g_M[t * 64 + c] = acc;
    }
}

// ---------------------------------------------------------------------------
// Precompute sin/cos tables: arg computed in fp32 (bit-matching the reference),
// transcendental evaluated in double (immune to --use_fast_math __sinf).
// ---------------------------------------------------------------------------
__global__ void sincos_kernel(const float* __restrict__ inv_freq) {
    int idx = blockIdx.x * blockDim.x + threadIdx.x;
    if (idx >= S_LEN * ROTN) return;
    int s = idx >> 5, f = idx & 31;
    float v = (float)s * inv_freq[f];
    g_sin[idx] = (float)sin((double)v);
    g_cos[idx] = (float)cos((double)v);
}

// ---------------------------------------------------------------------------
// Main kernel: per 128-row block, y = x @ M' (64x64) with packed f32x2 FMAs,
// then RoPE epilogue. Threads: 128; frag = 8 rows x 8 cols (4 "a" + 4 "b").
// Shared: sXT[64][128] transposed+swizzled x tile, sMd[64][160] duplicated M.
// ---------------------------------------------------------------------------
__device__ __forceinline__ void ffma2(unsigned long long& d,
                                      unsigned long long a,
                                      unsigned long long b) {
    asm("fma.rn.f32x2 %0, %1, %2, %0;" : "+l"(d) : "l"(a), "l"(b));
}
__device__ __forceinline__ float lo32(unsigned long long u) {
    return __uint_as_float((unsigned int)u);
}
__device__ __forceinline__ float hi32(unsigned long long u) {
    return __uint_as_float((unsigned int)(u >> 32));
}

__global__ void __launch_bounds__(128, 3)
cre_main_kernel(const float* __restrict__ x, float* __restrict__ out) {
    extern __shared__ float smem[];
    float* sXT = smem;              // 64 * 128 floats (32 KB), swizzled
    float* sMd = smem + 64 * 128;   // 64 * 160 floats (40 KB), duplicated M

    const int tid = threadIdx.x;
    const size_t rowBase = (size_t)blockIdx.x * 128;

    // --- Stage M into shared, duplicated: group cb (20 floats, 16 used):
    //     [0..7]  = dup of a-cols 4cb..4cb+3, [8..15] = dup of b-cols.
    for (int idx = tid; idx < 64 * 64; idx += 128) {
        float v = g_M[idx];
        int k = idx >> 6, c = idx & 63;
        int cb, off;
        if (c < 32) { cb = c >> 2;              off = (c & 3) * 2; }
        else        { int cc = c - 32; cb = cc >> 2; off = 8 + (cc & 3) * 2; }
        float* p = sMd + k * 160 + cb * 20 + off;
        p[0] = v; p[1] = v;
    }

    // --- Load + transpose x tile (128 rows x 64 k) into sXT[k][*],
    //     4-row groups XOR-swizzled by (k>>2) for conflict-free LDS.128.
    const float4* X4 = (const float4*)(x + rowBase * 64);
    #pragma unroll
    for (int it = 0; it < 16; ++it) {
        int idx4 = tid + 128 * it;
        float4 v = X4[idx4];
        int r = idx4 >> 4, kq = idx4 & 15;
        int pos = ((((r >> 2) ^ kq) << 2) | (r & 3));
        sXT[(4 * kq + 0) * 128 + pos] = v.x;
        sXT[(4 * kq + 1) * 128 + pos] = v.y;
        sXT[(4 * kq + 2) * 128 + pos] = v.z;
        sXT[(4 * kq + 3) * 128 + pos] = v.w;
    }
    __syncthreads();

    const int colblk = tid & 7;    // 8 column blocks of (4 a-cols + 4 b-cols)
    const int rowblk = tid >> 3;   // 16 row blocks of 8 rows
    const int r0 = rowblk << 3;
    const int G0 = r0 >> 2;

    unsigned long long acc[4][8];  // 4 row-pairs x 8 cols, packed f32x2
    #pragma unroll
    for (int p = 0; p < 4; ++p)
        #pragma unroll
        for (int c = 0; c < 8; ++c) acc[p][c] = 0ull;

    #pragma unroll 8
    for (int k = 0; k < 64; ++k) {
        const int s = k >> 2;
        const float* xrow = sXT + k * 128;
        ulonglong2 xa = *(const ulonglong2*)(xrow + (((G0    ) ^ s) << 2));
        ulonglong2 xb = *(const ulonglong2*)(xrow + (((G0 + 1) ^ s) << 2));
        const float* mrow = sMd + k * 160 + colblk * 20;
        ulonglong2 m01 = *(const ulonglong2*)(mrow);
        ulonglong2 m23 = *(const ulonglong2*)(mrow + 4);
        ulonglong2 m45 = *(const ulonglong2*)(mrow + 8);
        ulonglong2 m67 = *(const ulonglong2*)(mrow + 12);
        unsigned long long xp[4] = { xa.x, xa.y, xb.x, xb.y };
        unsigned long long mv[8] = { m01.x, m01.y, m23.x, m23.y,
                                     m45.x, m45.y, m67.x, m67.y };
        #pragma unroll
        for (int p = 0; p < 4; ++p)
            #pragma unroll
            for (int c = 0; c < 8; ++c)
                ffma2(acc[p][c], xp[p], mv[c]);
    }

    // --- RoPE epilogue. All 8 rows of this thread share one position s.
    const int c0 = colblk << 2;
    const size_t Rb = rowBase + r0;
    const int spos = (int)((Rb >> 4) & (S_LEN - 1));
    float4 sn4 = *(const float4*)(g_sin + spos * ROTN + c0);
    float4 cs4 = *(const float4*)(g_cos + spos * ROTN + c0);
    float snv[4] = { sn4.x, sn4.y, sn4.z, sn4.w };
    float csv[4] = { cs4.x, cs4.y, cs4.z, cs4.w };

    #pragma unroll
    for (int p = 0; p < 4; ++p) {
        float* o = out + (Rb + 2 * (size_t)p) * 64;
        // low halves -> row Rb + 2p
        {
            float a0 = lo32(acc[p][0]), a1 = lo32(acc[p][1]),
                  a2 = lo32(acc[p][2]), a3 = lo32(acc[p][3]);
            float b0 = lo32(acc[p][4]), b1 = lo32(acc[p][5]),
                  b2 = lo32(acc[p][6]), b3 = lo32(acc[p][7]);
            float4 ra = make_float4(a0 * csv[0] - b0 * snv[0],
                                    a1 * csv[1] - b1 * snv[1],
                                    a2 * csv[2] - b2 * snv[2],
                                    a3 * csv[3] - b3 * snv[3]);
            float4 rb = make_float4(a0 * snv[0] + b0 * csv[0],
                                    a1 * snv[1] + b1 * csv[1],
                                    a2 * snv[2] + b2 * csv[2],
                                    a3 * snv[3] + b3 * csv[3]);
            *(float4*)(o + c0)      = ra;
            *(float4*)(o + 32 + c0) = rb;
        }
        // high halves -> row Rb + 2p + 1
        {
            float a0 = hi32(acc[p][0]), a1 = hi32(acc[p][1]),
                  a2 = hi32(acc[p][2]), a3 = hi32(acc[p][3]);
            float b0 = hi32(acc[p][4]), b1 = hi32(acc[p][5]),
                  b2 = hi32(acc[p][6]), b3 = hi32(acc[p][7]);
            float4 ra = make_float4(a0 * csv[0] - b0 * snv[0],
                                    a1 * csv[1] - b1 * snv[1],
                                    a2 * csv[2] - b2 * snv[2],
                                    a3 * csv[3] - b3 * snv[3]);
            float4 rb = make_float4(a0 * snv[0] + b0 * csv[0],
                                    a1 * snv[1] + b1 * csv[1],
                                    a2 * snv[2] + b2 * csv[2],
                                    a3 * snv[3] + b3 * csv[3]);
            *(float4*)(o + 64 + c0)      = ra;
            *(float4*)(o + 64 + 32 + c0) = rb;
        }
    }
}

// ---------------------------------------------------------------------------
extern "C" void kernel_launch(void* const* d_in, const int* in_sizes, int n_in,
                              void* d_out, int out_size) {
    const float* x      = (const float*)d_in[0];
    const float* thetas = (const float*)d_in[1];
    const float* tscale = (const float*)d_in[2];
    const float* rmat   = (const float*)d_in[3];
    const float* invf   = (const float*)d_in[4];
    const int*   pairs  = (const int*)d_in[5];
    float*       out    = (float*)d_out;

    const int smem_bytes = (64 * 128 + 64 * 160) * (int)sizeof(float);  // 73728
    cudaFuncSetAttribute(cre_main_kernel,
                         cudaFuncAttributeMaxDynamicSharedMemorySize, smem_bytes);

    precomp_M_kernel<<<1, 64>>>(thetas, tscale, rmat, pairs);
    sincos_kernel<<<(S_LEN * ROTN) / 256, 256>>>(invf);

    int rows = in_sizes[0] / 64;          // 524288
    int blocks = rows / 128;              // 4096
    cre_main_kernel<<<blocks, 128, smem_bytes>>>(x, out);
}

// round 2
// speedup vs baseline: 1.7475x; 1.7475x over previous
#include <cuda_runtime.h>
#include <cstdint>

#define S_LEN 4096
#define ROTN  32

// Precomputed combined 64x64 matrix (column-permuted: cols 0..31 = original even
// output cols, 32..63 = original odd output cols), and RoPE sin/cos tables.
__device__ float g_M[64 * 64];
__device__ float g_sin[S_LEN * ROTN];
__device__ float g_cos[S_LEN * ROTN];

// ---------------------------------------------------------------------------
// Precompute M = B_total @ r_matrix (with epilogue column permutation).
// One block, 256 threads. All heavy data staged in shared; fp32 trig (args are
// tiny: |theta*scale| ~ 0.3, so even __sinf is exact to ~1e-7).
// ---------------------------------------------------------------------------
__global__ void __launch_bounds__(256, 1)
precomp_M_kernel(const float* __restrict__ thetas,
                 const float* __restrict__ theta_scale,
                 const float* __restrict__ rmat,
                 const int*   __restrict__ pairs) {
    __shared__ float E[64][64];    // row-operator accumulator
    __shared__ float R[64][64];    // rmat with column permutation applied
    __shared__ float CS[ROTN][2];  // (cos, sin) per step
    __shared__ int   PJ[ROTN][2];  // (i, j) per step

    const int tid = threadIdx.x;

    // Stage permuted rmat: R[k][c] = rmat[k*64 + perm(c)]
    for (int idx = tid; idx < 64 * 64; idx += 256) {
        int k = idx >> 6, c = idx & 63;
        int pc = (c < 32) ? (2 * c) : (2 * (c - 32) + 1);
        R[k][c] = rmat[k * 64 + pc];
    }
    // Stage step constants
    if (tid < ROTN) {
        float th = thetas[tid] * theta_scale[0];
        CS[tid][0] = cosf(th);
        CS[tid][1] = sinf(th);
        PJ[tid][0] = pairs[2 * tid];
        PJ[tid][1] = pairs[2 * tid + 1];
    }
    // Init E = I
    for (int idx = tid; idx < 64 * 64; idx += 256) {
        int k = idx >> 6, c = idx & 63;
        E[k][c] = (k == c) ? 1.0f : 0.0f;
    }
    __syncthreads();

    // Sequential blended-rotation scan: thread t (<64) owns row t of E.
    if (tid < 64) {
        #pragma unroll
        for (int s = 0; s < ROTN; ++s) {
            int i = PJ[s][0], j = PJ[s][1];
            float cth = CS[s][0], sth = CS[s][1];
            float xi = E[tid][i], xj = E[tid][j];
            float gi =  xi * cth + xj * sth;
            float gj = -xi * sth + xj * cth;
            float ni = (2.0f * gi + xi - 2.0f * gi * cth) * (1.0f / 3.0f);
            float nj = (2.0f * gj + xj - 2.0f * gi * sth) * (1.0f / 3.0f);
            E[tid][i] = ni;
            E[tid][j] = nj;
        }
    }
    __syncthreads();

    // M = E @ R, all-shared. 256 threads x 16 outputs each.
    // Warp lanes share a row (E broadcast) and take consecutive cols (R c-f).
    for (int idx = tid; idx < 64 * 64; idx += 256) {
        int t = idx >> 6, c = idx & 63;
        float acc = 0.0f;
        #pragma unroll
        for (int k = 0; k < 64; ++k) acc = fmaf(E[t][k], R[k][c], acc);
        g_M[t * 64 + c] = acc;
    }
}

// ---------------------------------------------------------------------------
// Precompute sin/cos tables: arg computed in fp32 (bit-matching the reference),
// transcendental evaluated in double (args reach ~4095; fast-math fp32 sin
// would lose ~1e-3 absolute there).
// ---------------------------------------------------------------------------
__global__ void sincos_kernel(const float* __restrict__ inv_freq) {
    int idx = blockIdx.x * blockDim.x + threadIdx.x;
    if (idx >= S_LEN * ROTN) return;
    int s = idx >> 5, f = idx & 31;
    float v = (float)s * inv_freq[f];
    g_sin[idx] = (float)sin((double)v);
    g_cos[idx] = (float)cos((double)v);
}

// ---------------------------------------------------------------------------
// Main kernel: per 128-row block, y = x @ M' (64x64) with packed f32x2 FMAs,
// then RoPE epilogue. Threads: 128; frag = 8 rows x 8 cols (4 "a" + 4 "b").
// Shared: sXT[64][128] transposed+swizzled x tile, sMd[64][160] duplicated M.
// ---------------------------------------------------------------------------
__device__ __forceinline__ void ffma2(unsigned long long& d,
                                      unsigned long long a,
                                      unsigned long long b) {
    asm("fma.rn.f32x2 %0, %1, %2, %0;" : "+l"(d) : "l"(a), "l"(b));
}
__device__ __forceinline__ float lo32(unsigned long long u) {
    return __uint_as_float((unsigned int)u);
}
__device__ __forceinline__ float hi32(unsigned long long u) {
    return __uint_as_float((unsigned int)(u >> 32));
}

__global__ void __launch_bounds__(128, 3)
cre_main_kernel(const float* __restrict__ x, float* __restrict__ out) {
    extern __shared__ float smem[];
    float* sXT = smem;              // 64 * 128 floats (32 KB), swizzled
    float* sMd = smem + 64 * 128;   // 64 * 160 floats (40 KB), duplicated M

    const int tid = threadIdx.x;
    const size_t rowBase = (size_t)blockIdx.x * 128;

    // --- Stage M into shared, duplicated: group cb (20 floats, 16 used):
    //     [0..7]  = dup of a-cols 4cb..4cb+3, [8..15] = dup of b-cols.
    for (int idx = tid; idx < 64 * 64; idx += 128) {
        float v = g_M[idx];
        int k = idx >> 6, c = idx & 63;
        int cb, off;
        if (c < 32) { cb = c >> 2;              off = (c & 3) * 2; }
        else        { int cc = c - 32; cb = cc >> 2; off = 8 + (cc & 3) * 2; }
        float* p = sMd + k * 160 + cb * 20 + off;
        p[0] = v; p[1] = v;
    }

    // --- Load + transpose x tile (128 rows x 64 k) into sXT[k][*],
    //     4-row groups XOR-swizzled by (k>>2) for conflict-free LDS.128.
    const float4* X4 = (const float4*)(x + rowBase * 64);
    #pragma unroll
    for (int it = 0; it < 16; ++it) {
        int idx4 = tid + 128 * it;
        float4 v = X4[idx4];
        int r = idx4 >> 4, kq = idx4 & 15;
        int pos = ((((r >> 2) ^ kq) << 2) | (r & 3));
        sXT[(4 * kq + 0) * 128 + pos] = v.x;
        sXT[(4 * kq + 1) * 128 + pos] = v.y;
        sXT[(4 * kq + 2) * 128 + pos] = v.z;
        sXT[(4 * kq + 3) * 128 + pos] = v.w;
    }
    __syncthreads();

    const int colblk = tid & 7;    // 8 column blocks of (4 a-cols + 4 b-cols)
    const int rowblk = tid >> 3;   // 16 row blocks of 8 rows
    const int r0 = rowblk << 3;
    const int G0 = r0 >> 2;

    unsigned long long acc[4][8];  // 4 row-pairs x 8 cols, packed f32x2
    #pragma unroll
    for (int p = 0; p < 4; ++p)
        #pragma unroll
        for (int c = 0; c < 8; ++c) acc[p][c] = 0ull;

    #pragma unroll 8
    for (int k = 0; k < 64; ++k) {
        const int s = k >> 2;
        const float* xrow = sXT + k * 128;
        ulonglong2 xa = *(const ulonglong2*)(xrow + (((G0    ) ^ s) << 2));
        ulonglong2 xb = *(const ulonglong2*)(xrow + (((G0 + 1) ^ s) << 2));
        const float* mrow = sMd + k * 160 + colblk * 20;
        ulonglong2 m01 = *(const ulonglong2*)(mrow);
        ulonglong2 m23 = *(const ulonglong2*)(mrow + 4);
        ulonglong2 m45 = *(const ulonglong2*)(mrow + 8);
        ulonglong2 m67 = *(const ulonglong2*)(mrow + 12);
        unsigned long long xp[4] = { xa.x, xa.y, xb.x, xb.y };
        unsigned long long mv[8] = { m01.x, m01.y, m23.x, m23.y,
                                     m45.x, m45.y, m67.x, m67.y };
        #pragma unroll
        for (int p = 0; p < 4; ++p)
            #pragma unroll
            for (int c = 0; c < 8; ++c)
                ffma2(acc[p][c], xp[p], mv[c]);
    }

    // --- RoPE epilogue. All 8 rows of this thread share one position s.
    const int c0 = colblk << 2;
    const size_t Rb = rowBase + r0;
    const int spos = (int)((Rb >> 4) & (S_LEN - 1));
    float4 sn4 = *(const float4*)(g_sin + spos * ROTN + c0);
    float4 cs4 = *(const float4*)(g_cos + spos * ROTN + c0);
    float snv[4] = { sn4.x, sn4.y, sn4.z, sn4.w };
    float csv[4] = { cs4.x, cs4.y, cs4.z, cs4.w };

    #pragma unroll
    for (int p = 0; p < 4; ++p) {
        float* o = out + (Rb + 2 * (size_t)p) * 64;
        // low halves -> row Rb + 2p
        {
            float a0 = lo32(acc[p][0]), a1 = lo32(acc[p][1]),
                  a2 = lo32(acc[p][2]), a3 = lo32(acc[p][3]);
            float b0 = lo32(acc[p][4]), b1 = lo32(acc[p][5]),
                  b2 = lo32(acc[p][6]), b3 = lo32(acc[p][7]);
            float4 ra = make_float4(a0 * csv[0] - b0 * snv[0],
                                    a1 * csv[1] - b1 * snv[1],
                                    a2 * csv[2] - b2 * snv[2],
                                    a3 * csv[3] - b3 * snv[3]);
            float4 rb = make_float4(a0 * snv[0] + b0 * csv[0],
                                    a1 * snv[1] + b1 * csv[1],
                                    a2 * snv[2] + b2 * csv[2],
                                    a3 * snv[3] + b3 * csv[3]);
            *(float4*)(o + c0)      = ra;
            *(float4*)(o + 32 + c0) = rb;
        }
        // high halves -> row Rb + 2p + 1
        {
            float a0 = hi32(acc[p][0]), a1 = hi32(acc[p][1]),
                  a2 = hi32(acc[p][2]), a3 = hi32(acc[p][3]);
            float b0 = hi32(acc[p][4]), b1 = hi32(acc[p][5]),
                  b2 = hi32(acc[p][6]), b3 = hi32(acc[p][7]);
            float4 ra = make_float4(a0 * csv[0] - b0 * snv[0],
                                    a1 * csv[1] - b1 * snv[1],
                                    a2 * csv[2] - b2 * snv[2],
                                    a3 * csv[3] - b3 * snv[3]);
            float4 rb = make_float4(a0 * snv[0] + b0 * csv[0],
                                    a1 * snv[1] + b1 * csv[1],
                                    a2 * snv[2] + b2 * csv[2],
                                    a3 * snv[3] + b3 * csv[3]);
            *(float4*)(o + 64 + c0)      = ra;
            *(float4*)(o + 64 + 32 + c0) = rb;
        }
    }
}

// ---------------------------------------------------------------------------
extern "C" void kernel_launch(void* const* d_in, const int* in_sizes, int n_in,
                              void* d_out, int out_size) {
    const float* x      = (const float*)d_in[0];
    const float* thetas = (const float*)d_in[1];
    const float* tscale = (const float*)d_in[2];
    const float* rmat   = (const float*)d_in[3];
    const float* invf   = (const float*)d_in[4];
    const int*   pairs  = (const int*)d_in[5];
    float*       out    = (float*)d_out;

    const int smem_bytes = (64 * 128 + 64 * 160) * (int)sizeof(float);  // 73728
    cudaFuncSetAttribute(cre_main_kernel,
                         cudaFuncAttributeMaxDynamicSharedMemorySize, smem_bytes);

    precomp_M_kernel<<<1, 256>>>(thetas, tscale, rmat, pairs);
    sincos_kernel<<<(S_LEN * ROTN) / 256, 256>>>(invf);

    int rows = in_sizes[0] / 64;          // 524288
    int blocks = rows / 128;              // 4096
    cre_main_kernel<<<blocks, 128, smem_bytes>>>(x, out);
}

// round 5
// speedup vs baseline: 3.0218x; 1.7292x over previous
#include <cuda_runtime.h>
#include <cstdint>

#define S_LEN 4096
#define ROTN  32

// Combined 64x64 matrix (cols permuted: 0..31 = even outputs, 32..63 = odd),
// plus RoPE sin/cos tables.
__device__ float g_M[64 * 64];
__device__ float g_sin[S_LEN * ROTN];
__device__ float g_cos[S_LEN * ROTN];

__device__ __forceinline__ uint32_t f2tf32(float f) {
    uint32_t o;
    asm("cvt.rna.satfinite.tf32.f32 %0, %1;" : "=r"(o) : "f"(f));
    return o;
}

// ============================ precompute ===================================
__global__ void __launch_bounds__(256, 1)
precomp_M_kernel(const float* __restrict__ thetas,
                 const float* __restrict__ theta_scale,
                 const float* __restrict__ rmat,
                 const int*   __restrict__ pairs) {
    __shared__ float ET[64][65];   // transposed operator: ET[k][t] = E[t][k]
    __shared__ float R[64][64];    // rmat, column-permuted
    __shared__ float CS[ROTN][2];
    __shared__ int   PJ[ROTN][2];
    const int tid = threadIdx.x;

    for (int idx = tid; idx < 64 * 64; idx += 256) {
        int k = idx >> 6, c = idx & 63;
        int pc = (c < 32) ? (2 * c) : (2 * (c - 32) + 1);
        R[k][c] = rmat[k * 64 + pc];
    }
    if (tid < ROTN) {
        float th = thetas[tid] * theta_scale[0];
        CS[tid][0] = cosf(th);
        CS[tid][1] = sinf(th);
        PJ[tid][0] = pairs[2 * tid];
        PJ[tid][1] = pairs[2 * tid + 1];
    }
    for (int idx = tid; idx < 64 * 64; idx += 256) {
        int k = idx >> 6, t = idx & 63;
        ET[k][t] = (k == t) ? 1.0f : 0.0f;
    }
    __syncthreads();

    if (tid < 64) {
        #pragma unroll
        for (int s = 0; s < ROTN; ++s) {
            int i = PJ[s][0], j = PJ[s][1];
            float cth = CS[s][0], sth = CS[s][1];
            float xi = ET[i][tid], xj = ET[j][tid];
            float gi =  xi * cth + xj * sth;
            float gj = -xi * sth + xj * cth;
            ET[i][tid] = (2.0f * gi + xi - 2.0f * gi * cth) * (1.0f / 3.0f);
            ET[j][tid] = (2.0f * gj + xj - 2.0f * gi * sth) * (1.0f / 3.0f);
        }
    }
    __syncthreads();

    // M = E @ R with 16 independent accumulators per thread (k-outer).
    const int t = tid & 63, g = tid >> 6, c0 = g * 16;
    float acc[16];
    #pragma unroll
    for (int i = 0; i < 16; ++i) acc[i] = 0.0f;
    #pragma unroll 4
    for (int k = 0; k < 64; ++k) {
        float e = ET[k][t];
        float4 r0 = *(const float4*)&R[k][c0];
        float4 r1 = *(const float4*)&R[k][c0 + 4];
        float4 r2 = *(const float4*)&R[k][c0 + 8];
        float4 r3 = *(const float4*)&R[k][c0 + 12];
        acc[0]  = fmaf(e, r0.x, acc[0]);   acc[1]  = fmaf(e, r0.y, acc[1]);
        acc[2]  = fmaf(e, r0.z, acc[2]);   acc[3]  = fmaf(e, r0.w, acc[3]);
        acc[4]  = fmaf(e, r1.x, acc[4]);   acc[5]  = fmaf(e, r1.y, acc[5]);
        acc[6]  = fmaf(e, r1.z, acc[6]);   acc[7]  = fmaf(e, r1.w, acc[7]);
        acc[8]  = fmaf(e, r2.x, acc[8]);   acc[9]  = fmaf(e, r2.y, acc[9]);
        acc[10] = fmaf(e, r2.z, acc[10]);  acc[11] = fmaf(e, r2.w, acc[11]);
        acc[12] = fmaf(e, r3.x, acc[12]);  acc[13] = fmaf(e, r3.y, acc[13]);
        acc[14] = fmaf(e, r3.z, acc[14]);  acc[15] = fmaf(e, r3.w, acc[15]);
    }
    #pragma unroll
    for (int i = 0; i < 16; ++i) g_M[t * 64 + c0 + i] = acc[i];
}

__global__ void sincos_kernel(const float* __restrict__ inv_freq) {
    int idx = blockIdx.x * blockDim.x + threadIdx.x;
    if (idx >= S_LEN * ROTN) return;
    int s = idx >> 5, f = idx & 31;
    float v = (float)s * inv_freq[f];     // fp32 arg, bit-matching reference
    double sd, cd;
    sincos((double)v, &sd, &cd);          // accurate under fast_math
    g_sin[idx] = (float)sd;
    g_cos[idx] = (float)cd;
}

// ============================ main kernel ==================================
// 128-row tile per CTA (4 warps). y = x @ M' via mma.sync m16n8k8 tf32
// ("fallback HMMA" — tcgen05 is not available at compute_103 PTX target).
// Warp w owns output n-tiles {w, w+4} = cols [8w,8w+8) and [32+8w,32+8w+8),
// whose B fragments live permanently in 32 registers. A fragments come from
// an SMEM x-tile with row stride 68 floats (bank = 4g+tig+const -> conflict-
// free scalar LDS). RoPE epilogue pairs col c with c+32 inside the thread.
#define XSTRIDE 68

__device__ __forceinline__ void mma16n8k8(float* c, const uint32_t* a,
                                          uint32_t b0, uint32_t b1) {
    asm volatile(
        "mma.sync.aligned.m16n8k8.row.col.f32.tf32.tf32.f32 "
        "{%0,%1,%2,%3}, {%4,%5,%6,%7}, {%8,%9}, {%0,%1,%2,%3};"
        : "+f"(c[0]), "+f"(c[1]), "+f"(c[2]), "+f"(c[3])
        : "r"(a[0]), "r"(a[1]), "r"(a[2]), "r"(a[3]), "r"(b0), "r"(b1));
}

__global__ void __launch_bounds__(128, 4)
cre_hmma_kernel(const float* __restrict__ x, float* __restrict__ out) {
    __shared__ uint32_t sX[128 * XSTRIDE];   // tf32-converted x tile, 34816 B

    const int tid  = threadIdx.x;
    const int w    = tid >> 5;
    const int lane = tid & 31;
    const int g    = lane >> 2;
    const int tig  = lane & 3;
    const size_t rowBase = (size_t)blockIdx.x * 128;

    // ---- Stage x tile: coalesced LDG.128, cvt to tf32, STS.128 ----
    {
        const float4* X4 = (const float4*)(x + rowBase * 64);
        #pragma unroll
        for (int it = 0; it < 16; ++it) {
            int idx4 = tid + 128 * it;
            float4 v = X4[idx4];
            int r = idx4 >> 4, q = idx4 & 15;
            uint32_t* p = sX + r * XSTRIDE + 4 * q;
            p[0] = f2tf32(v.x);
            p[1] = f2tf32(v.y);
            p[2] = f2tf32(v.z);
            p[3] = f2tf32(v.w);
        }
    }

    // ---- B fragments (constant per warp): n-tiles j0=w, j1=w+4 ----
    uint32_t bA[8][2], bB[8][2];
    {
        const int nA = 8 * w + g;          // col in M' for n-tile w
        const int nB = 32 + 8 * w + g;     // col for n-tile w+4
        #pragma unroll
        for (int s = 0; s < 8; ++s) {
            int k0 = 8 * s + tig, k1 = 8 * s + tig + 4;
            bA[s][0] = f2tf32(g_M[k0 * 64 + nA]);
            bA[s][1] = f2tf32(g_M[k1 * 64 + nA]);
            bB[s][0] = f2tf32(g_M[k0 * 64 + nB]);
            bB[s][1] = f2tf32(g_M[k1 * 64 + nB]);
        }
    }
    __syncthreads();

    const int cf = 8 * w + 2 * tig;        // freq/col index pair base

    #pragma unroll
    for (int mt = 0; mt < 8; ++mt) {
        // ---- GEMM for 16 rows x (8 a-cols + 8 b-cols) ----
        float cA[4] = {0.f, 0.f, 0.f, 0.f};
        float cB[4] = {0.f, 0.f, 0.f, 0.f};
        const uint32_t* xrow = sX + (mt * 16 + g) * XSTRIDE;
        #pragma unroll
        for (int s = 0; s < 8; ++s) {
            uint32_t a[4];
            a[0] = xrow[8 * s + tig];
            a[1] = xrow[8 * XSTRIDE + 8 * s + tig];
            a[2] = xrow[8 * s + tig + 4];
            a[3] = xrow[8 * XSTRIDE + 8 * s + tig + 4];
            mma16n8k8(cA, a, bA[s][0], bA[s][1]);
            mma16n8k8(cB, a, bB[s][0], bB[s][1]);
        }

        // ---- RoPE epilogue: rows R0+g and R0+8+g, cols cf, cf+1 ----
        const size_t R0 = rowBase + mt * 16;
        const int spos = (int)((R0 >> 4) & (S_LEN - 1));
        float2 sn = *(const float2*)(g_sin + spos * ROTN + cf);
        float2 cs = *(const float2*)(g_cos + spos * ROTN + cf);

        float* o1 = out + (R0 + g) * 64;
        float* o2 = out + (R0 + 8 + g) * 64;
        float2 v;
        v.x = cA[0] * cs.x - cB[0] * sn.x;
        v.y = cA[1] * cs.y - cB[1] * sn.y;
        *(float2*)(o1 + cf) = v;
        v.x = cA[0] * sn.x + cB[0] * cs.x;
        v.y = cA[1] * sn.y + cB[1] * cs.y;
        *(float2*)(o1 + 32 + cf) = v;
        v.x = cA[2] * cs.x - cB[2] * sn.x;
        v.y = cA[3] * cs.y - cB[3] * sn.y;
        *(float2*)(o2 + cf) = v;
        v.x = cA[2] * sn.x + cB[2] * cs.x;
        v.y = cA[3] * sn.y + cB[3] * cs.y;
        *(float2*)(o2 + 32 + cf) = v;
    }
}

// ---------------------------------------------------------------------------
extern "C" void kernel_launch(void* const* d_in, const int* in_sizes, int n_in,
                              void* d_out, int out_size) {
    const float* x      = (const float*)d_in[0];
    const float* thetas = (const float*)d_in[1];
    const float* tscale = (const float*)d_in[2];
    const float* rmat   = (const float*)d_in[3];
    const float* invf   = (const float*)d_in[4];
    const int*   pairs  = (const int*)d_in[5];
    float*       out    = (float*)d_out;

    precomp_M_kernel<<<1, 256>>>(thetas, tscale, rmat, pairs);
    sincos_kernel<<<(S_LEN * ROTN) / 256, 256>>>(invf);

    int rows   = in_sizes[0] / 64;     // 524288
    int blocks = rows / 128;           // 4096
    cre_hmma_kernel<<<blocks, 128>>>(x, out);
}

// round 6
// speedup vs baseline: 3.5313x; 1.1686x over previous
#include <cuda_runtime.h>
#include <cstdint>

#define S_LEN 4096
#define ROTN  32

// Combined 64x64 matrix M' (cols permuted: 0..31 = even outputs, 32..63 = odd),
// plus RoPE sin/cos tables.
__device__ float g_M[64 * 64];
__device__ float g_sin[S_LEN * ROTN];
__device__ float g_cos[S_LEN * ROTN];

__device__ __forceinline__ uint32_t f2tf32(float f) {
    uint32_t o;
    asm("cvt.rna.satfinite.tf32.f32 %0, %1;" : "=r"(o) : "f"(f));
    return o;
}
__device__ __forceinline__ uint32_t smem_u32(const void* p) {
    uint32_t a;
    asm("{ .reg .u64 t; cvta.to.shared.u64 t, %1; cvt.u32.u64 %0, t; }"
        : "=r"(a) : "l"(p));
    return a;
}

// ============================ setup kernel =================================
// Block 0: compute M' = B1*...*B32*R_perm directly via reversed row-op scan
//          (no 64^3 matmul needed). Thread t owns column t — fully parallel.
// Blocks 1..512: RoPE sin/cos tables (fp32 args, fp64 transcendental).
__global__ void __launch_bounds__(256, 1)
setup_kernel(const float* __restrict__ thetas,
             const float* __restrict__ theta_scale,
             const float* __restrict__ rmat,
             const int*   __restrict__ pairs,
             const float* __restrict__ inv_freq) {
    const int tid = threadIdx.x;

    if (blockIdx.x != 0) {
        int idx = (blockIdx.x - 1) * 256 + tid;   // 512*256 = 131072 = S_LEN*ROTN
        int s = idx >> 5, f = idx & 31;
        float v = (float)s * inv_freq[f];          // fp32 arg, matches reference
        double sd, cd;
        sincos((double)v, &sd, &cd);               // accurate under fast_math
        g_sin[idx] = (float)sd;
        g_cos[idx] = (float)cd;
        return;
    }

    __shared__ float Ms[64][65];     // M under construction: Ms[row=k][col=n]
    __shared__ float AB[ROTN][4];    // (alpha, beta, gamma, delta) per step
    __shared__ int   PJ[ROTN][2];

    // Stage R with the epilogue column permutation applied.
    for (int idx = tid; idx < 64 * 64; idx += 256) {
        int k = idx >> 6, c = idx & 63;
        int pc = (c < 32) ? (2 * c) : (2 * (c - 32) + 1);
        Ms[k][c] = rmat[k * 64 + pc];
    }
    if (tid < ROTN) {
        float th = thetas[tid] * theta_scale[0];
        float c = cosf(th), s = sinf(th);
        AB[tid][0] = (1.0f + 2.0f * c - 2.0f * c * c) * (1.0f / 3.0f);  // alpha
        AB[tid][1] = (2.0f * s - 2.0f * s * c) * (1.0f / 3.0f);         // beta
        AB[tid][2] = -(2.0f * s + 2.0f * c * s) * (1.0f / 3.0f);        // gamma
        AB[tid][3] = (2.0f * c + 1.0f - 2.0f * s * s) * (1.0f / 3.0f);  // delta
        PJ[tid][0] = pairs[2 * tid];
        PJ[tid][1] = pairs[2 * tid + 1];
    }
    __syncthreads();

    // Reversed scan: M <- B_s * M for s = 32..1. Row ops on rows (i, j);
    // thread t < 64 owns column t independently (no syncs needed inside).
    if (tid < 64) {
        #pragma unroll
        for (int s = ROTN - 1; s >= 0; --s) {
            int i = PJ[s][0], j = PJ[s][1];
            float a = AB[s][0], b = AB[s][1], gm = AB[s][2], d = AB[s][3];
            float mi = Ms[i][tid], mj = Ms[j][tid];
            Ms[i][tid] = a * mi + gm * mj;
            Ms[j][tid] = b * mi + d * mj;
        }
    }
    __syncthreads();

    for (int idx = tid; idx < 64 * 64; idx += 256) {
        int k = idx >> 6, c = idx & 63;
        g_M[idx] = Ms[k][c];
    }
}

// ============================ main kernel ==================================
// 128-row tile per CTA (4 warps). y = x @ M' via mma.sync m16n8k8 tf32.
// Staging: raw fp32 via cp.async (16B), cvt.rna applied after LDS (identical
// numerics to converting at staging). Warp w owns n-tiles {w, w+4} = cols
// [8w,8w+8) and [32+8w,+8); B fragments live in 32 registers. SMEM row stride
// 68 floats -> conflict-free scalar LDS. RoPE pairs col c with c+32 in-thread.
#define XSTRIDE 68

__device__ __forceinline__ void mma16n8k8(float* c, const uint32_t* a,
                                          uint32_t b0, uint32_t b1) {
    asm volatile(
        "mma.sync.aligned.m16n8k8.row.col.f32.tf32.tf32.f32 "
        "{%0,%1,%2,%3}, {%4,%5,%6,%7}, {%8,%9}, {%0,%1,%2,%3};"
        : "+f"(c[0]), "+f"(c[1]), "+f"(c[2]), "+f"(c[3])
        : "r"(a[0]), "r"(a[1]), "r"(a[2]), "r"(a[3]), "r"(b0), "r"(b1));
}

__global__ void __launch_bounds__(128, 6)
cre_hmma_kernel(const float* __restrict__ x, float* __restrict__ out) {
    __shared__ uint32_t sX[128 * XSTRIDE];   // raw fp32 x tile, 34816 B

    const int tid  = threadIdx.x;
    const int w    = tid >> 5;
    const int lane = tid & 31;
    const int g    = lane >> 2;
    const int tig  = lane & 3;
    const size_t rowBase = (size_t)blockIdx.x * 128;

    // ---- Stage x tile with cp.async (no register round-trip) ----
    {
        const float4* X4 = (const float4*)(x + rowBase * 64);
        const uint32_t sbase = smem_u32(sX);
        #pragma unroll
        for (int it = 0; it < 16; ++it) {
            int idx4 = tid + 128 * it;
            int r = idx4 >> 4, q = idx4 & 15;
            uint32_t dst = sbase + (uint32_t)(r * XSTRIDE + 4 * q) * 4u;
            asm volatile("cp.async.cg.shared.global [%0], [%1], 16;"
                         :: "r"(dst), "l"(X4 + idx4));
        }
        asm volatile("cp.async.commit_group;" ::: "memory");
    }

    // ---- B fragments (constant per warp) while loads are in flight ----
    uint32_t bA[8][2], bB[8][2];
    {
        const int nA = 8 * w + g;          // col in M' for n-tile w
        const int nB = 32 + 8 * w + g;     // col for n-tile w+4
        #pragma unroll
        for (int s = 0; s < 8; ++s) {
            int k0 = 8 * s + tig, k1 = 8 * s + tig + 4;
            bA[s][0] = f2tf32(g_M[k0 * 64 + nA]);
            bA[s][1] = f2tf32(g_M[k1 * 64 + nA]);
            bB[s][0] = f2tf32(g_M[k0 * 64 + nB]);
            bB[s][1] = f2tf32(g_M[k1 * 64 + nB]);
        }
    }
    asm volatile("cp.async.wait_group 0;" ::: "memory");
    __syncthreads();

    const int cf = 8 * w + 2 * tig;        // freq/col pair base

    #pragma unroll
    for (int mt = 0; mt < 8; ++mt) {
        // ---- GEMM for 16 rows x (8 a-cols + 8 b-cols) ----
        float cA[4] = {0.f, 0.f, 0.f, 0.f};
        float cB[4] = {0.f, 0.f, 0.f, 0.f};
        const uint32_t* xrow = sX + (mt * 16 + g) * XSTRIDE;
        #pragma unroll
        for (int s = 0; s < 8; ++s) {
            uint32_t a[4];
            a[0] = f2tf32(__uint_as_float(xrow[8 * s + tig]));
            a[1] = f2tf32(__uint_as_float(xrow[8 * XSTRIDE + 8 * s + tig]));
            a[2] = f2tf32(__uint_as_float(xrow[8 * s + tig + 4]));
            a[3] = f2tf32(__uint_as_float(xrow[8 * XSTRIDE + 8 * s + tig + 4]));
            mma16n8k8(cA, a, bA[s][0], bA[s][1]);
            mma16n8k8(cB, a, bB[s][0], bB[s][1]);
        }

        // ---- RoPE epilogue: rows R0+g and R0+8+g, cols cf, cf+1 ----
        const size_t R0 = rowBase + mt * 16;
        const int spos = (int)((R0 >> 4) & (S_LEN - 1));
        float2 sn = *(const float2*)(g_sin + spos * ROTN + cf);
        float2 cs = *(const float2*)(g_cos + spos * ROTN + cf);

        float* o1 = out + (R0 + g) * 64;
        float* o2 = out + (R0 + 8 + g) * 64;
        float2 v;
        v.x = cA[0] * cs.x - cB[0] * sn.x;
        v.y = cA[1] * cs.y - cB[1] * sn.y;
        *(float2*)(o1 + cf) = v;
        v.x = cA[0] * sn.x + cB[0] * cs.x;
        v.y = cA[1] * sn.y + cB[1] * cs.y;
        *(float2*)(o1 + 32 + cf) = v;
        v.x = cA[2] * cs.x - cB[2] * sn.x;
        v.y = cA[3] * cs.y - cB[3] * sn.y;
        *(float2*)(o2 + cf) = v;
        v.x = cA[2] * sn.x + cB[2] * cs.x;
        v.y = cA[3] * sn.y + cB[3] * cs.y;
        *(float2*)(o2 + 32 + cf) = v;
    }
}

// ---------------------------------------------------------------------------
extern "C" void kernel_launch(void* const* d_in, const int* in_sizes, int n_in,
                              void* d_out, int out_size) {
    const float* x      = (const float*)d_in[0];
    const float* thetas = (const float*)d_in[1];
    const float* tscale = (const float*)d_in[2];
    const float* rmat   = (const float*)d_in[3];
    const float* invf   = (const float*)d_in[4];
    const int*   pairs  = (const int*)d_in[5];
    float*       out    = (float*)d_out;

    // Block 0: M' scan; blocks 1..512: sin/cos tables (concurrent).
    setup_kernel<<<513, 256>>>(thetas, tscale, rmat, pairs, invf);

    int rows   = in_sizes[0] / 64;     // 524288
    int blocks = rows / 128;           // 4096
    cre_hmma_kernel<<<blocks, 128>>>(x, out);
}

// round 7
// speedup vs baseline: 3.6367x; 1.0298x over previous
#include <cuda_runtime.h>
#include <cstdint>

#define S_LEN 4096
#define ROTN  32

// Combined 64x64 matrix M' (cols permuted: 0..31 = even outputs, 32..63 = odd),
// plus RoPE sin/cos tables.
__device__ float g_M[64 * 64];
__device__ float g_sin[S_LEN * ROTN];
__device__ float g_cos[S_LEN * ROTN];

__device__ __forceinline__ uint32_t f2tf32(float f) {
    uint32_t o;
    asm("cvt.rna.satfinite.tf32.f32 %0, %1;" : "=r"(o) : "f"(f));
    return o;
}
__device__ __forceinline__ uint32_t smem_u32(const void* p) {
    uint32_t a;
    asm("{ .reg .u64 t; cvta.to.shared.u64 t, %1; cvt.u32.u64 %0, t; }"
        : "=r"(a) : "l"(p));
    return a;
}

// ============================ setup kernel =================================
// Block 0: compute M' = B1*...*B32*R_perm via reversed row-op scan.
// Blocks 1..512: RoPE sin/cos tables (fp32 args, fp64 transcendental).
__global__ void __launch_bounds__(256, 1)
setup_kernel(const float* __restrict__ thetas,
             const float* __restrict__ theta_scale,
             const float* __restrict__ rmat,
             const int*   __restrict__ pairs,
             const float* __restrict__ inv_freq) {
    const int tid = threadIdx.x;

    if (blockIdx.x != 0) {
        int idx = (blockIdx.x - 1) * 256 + tid;   // 512*256 = S_LEN*ROTN
        int s = idx >> 5, f = idx & 31;
        float v = (float)s * inv_freq[f];          // fp32 arg, matches reference
        double sd, cd;
        sincos((double)v, &sd, &cd);               // accurate under fast_math
        g_sin[idx] = (float)sd;
        g_cos[idx] = (float)cd;
        return;
    }

    __shared__ float Ms[64][65];
    __shared__ float AB[ROTN][4];
    __shared__ int   PJ[ROTN][2];

    for (int idx = tid; idx < 64 * 64; idx += 256) {
        int k = idx >> 6, c = idx & 63;
        int pc = (c < 32) ? (2 * c) : (2 * (c - 32) + 1);
        Ms[k][c] = rmat[k * 64 + pc];
    }
    if (tid < ROTN) {
        float th = thetas[tid] * theta_scale[0];
        float c = cosf(th), s = sinf(th);
        AB[tid][0] = (1.0f + 2.0f * c - 2.0f * c * c) * (1.0f / 3.0f);
        AB[tid][1] = (2.0f * s - 2.0f * s * c) * (1.0f / 3.0f);
        AB[tid][2] = -(2.0f * s + 2.0f * c * s) * (1.0f / 3.0f);
        AB[tid][3] = (2.0f * c + 1.0f - 2.0f * s * s) * (1.0f / 3.0f);
        PJ[tid][0] = pairs[2 * tid];
        PJ[tid][1] = pairs[2 * tid + 1];
    }
    __syncthreads();

    if (tid < 64) {
        #pragma unroll
        for (int s = ROTN - 1; s >= 0; --s) {
            int i = PJ[s][0], j = PJ[s][1];
            float a = AB[s][0], b = AB[s][1], gm = AB[s][2], d = AB[s][3];
            float mi = Ms[i][tid], mj = Ms[j][tid];
            Ms[i][tid] = a * mi + gm * mj;
            Ms[j][tid] = b * mi + d * mj;
        }
    }
    __syncthreads();

    for (int idx = tid; idx < 64 * 64; idx += 256) {
        int k = idx >> 6, c = idx & 63;
        g_M[idx] = Ms[k][c];
    }
}

// ============================ main kernel ==================================
// 128-row tile per CTA, 4 warps. Warp w owns n-pairs {2(w&1), 2(w&1)+1} and
// m-tiles {4(w>>1)..+3}: halves redundant A-fragment LDS traffic vs all-warps-
// all-m. k-permutation inside each mma k8-block (frag pos tig <-> k=8s+2tig,
// pos tig+4 <-> k=8s+2tig+1) makes A fragments contiguous 8B pairs -> LDS.64.
// XSTRIDE=72 floats (row stride 4 mod 16 in 8B banks) = conflict-free LDS.64.
#define XSTRIDE 72

__device__ __forceinline__ void mma16n8k8(float* c, const uint32_t* a,
                                          uint32_t b0, uint32_t b1) {
    asm volatile(
        "mma.sync.aligned.m16n8k8.row.col.f32.tf32.tf32.f32 "
        "{%0,%1,%2,%3}, {%4,%5,%6,%7}, {%8,%9}, {%0,%1,%2,%3};"
        : "+f"(c[0]), "+f"(c[1]), "+f"(c[2]), "+f"(c[3])
        : "r"(a[0]), "r"(a[1]), "r"(a[2]), "r"(a[3]), "r"(b0), "r"(b1));
}

__global__ void __launch_bounds__(128, 4)
cre_hmma_kernel(const float* __restrict__ x, float* __restrict__ out) {
    __shared__ uint32_t sX[128 * XSTRIDE];   // raw fp32 x tile, 36864 B

    const int tid  = threadIdx.x;
    const int w    = tid >> 5;
    const int lane = tid & 31;
    const int g    = lane >> 2;
    const int tig  = lane & 3;
    const int pw   = w & 1;        // n-pair group: pairs {2pw, 2pw+1}
    const int mh   = w >> 1;       // m-tile group: tiles {4mh .. 4mh+3}
    const size_t rowBase = (size_t)blockIdx.x * 128;

    // ---- Stage x tile with cp.async ----
    {
        const float4* X4 = (const float4*)(x + rowBase * 64);
        const uint32_t sbase = smem_u32(sX);
        #pragma unroll
        for (int it = 0; it < 16; ++it) {
            int idx4 = tid + 128 * it;
            int r = idx4 >> 4, q = idx4 & 15;
            uint32_t dst = sbase + (uint32_t)(r * XSTRIDE + 4 * q) * 4u;
            asm volatile("cp.async.cg.shared.global [%0], [%1], 16;"
                         :: "r"(dst), "l"(X4 + idx4));
        }
        asm volatile("cp.async.commit_group;" ::: "memory");
    }

    // ---- B fragments for 2 n-pairs, k-permuted indexing ----
    uint32_t bA[2][8][2], bB[2][8][2];
    #pragma unroll
    for (int pp = 0; pp < 2; ++pp) {
        const int p  = 2 * pw + pp;
        const int nA = 8 * p + g;
        const int nB = 32 + 8 * p + g;
        #pragma unroll
        for (int s = 0; s < 8; ++s) {
            int k0 = 8 * s + 2 * tig, k1 = k0 + 1;
            bA[pp][s][0] = f2tf32(g_M[k0 * 64 + nA]);
            bA[pp][s][1] = f2tf32(g_M[k1 * 64 + nA]);
            bB[pp][s][0] = f2tf32(g_M[k0 * 64 + nB]);
            bB[pp][s][1] = f2tf32(g_M[k1 * 64 + nB]);
        }
    }
    asm volatile("cp.async.wait_group 0;" ::: "memory");
    __syncthreads();

    #pragma unroll
    for (int ml = 0; ml < 4; ++ml) {
        const int mt = 4 * mh + ml;
        float cA[2][4] = {{0.f,0.f,0.f,0.f},{0.f,0.f,0.f,0.f}};
        float cB[2][4] = {{0.f,0.f,0.f,0.f},{0.f,0.f,0.f,0.f}};
        const uint32_t* xlow  = sX + (mt * 16 + g) * XSTRIDE + 2 * tig;
        const uint32_t* xhigh = xlow + 8 * XSTRIDE;

        #pragma unroll
        for (int s = 0; s < 8; ++s) {
            uint2 lo = *(const uint2*)(xlow  + 8 * s);
            uint2 hi = *(const uint2*)(xhigh + 8 * s);
            uint32_t a[4];
            a[0] = f2tf32(__uint_as_float(lo.x));   // row g,   k=8s+2tig
            a[1] = f2tf32(__uint_as_float(hi.x));   // row g+8, k=8s+2tig
            a[2] = f2tf32(__uint_as_float(lo.y));   // row g,   k=8s+2tig+1
            a[3] = f2tf32(__uint_as_float(hi.y));   // row g+8, k=8s+2tig+1
            #pragma unroll
            for (int pp = 0; pp < 2; ++pp) {
                mma16n8k8(cA[pp], a, bA[pp][s][0], bA[pp][s][1]);
                mma16n8k8(cB[pp], a, bB[pp][s][0], bB[pp][s][1]);
            }
        }

        // ---- RoPE epilogue ----
        const size_t R0 = rowBase + mt * 16;
        const int spos = (int)((R0 >> 4) & (S_LEN - 1));
        float* o1 = out + (R0 + g) * 64;
        float* o2 = out + (R0 + 8 + g) * 64;

        #pragma unroll
        for (int pp = 0; pp < 2; ++pp) {
            const int p  = 2 * pw + pp;
            const int cf = 8 * p + 2 * tig;
            float2 sn = *(const float2*)(g_sin + spos * ROTN + cf);
            float2 cs = *(const float2*)(g_cos + spos * ROTN + cf);
            float2 v;
            v.x = cA[pp][0] * cs.x - cB[pp][0] * sn.x;
            v.y = cA[pp][1] * cs.y - cB[pp][1] * sn.y;
            *(float2*)(o1 + cf) = v;
            v.x = cA[pp][0] * sn.x + cB[pp][0] * cs.x;
            v.y = cA[pp][1] * sn.y + cB[pp][1] * cs.y;
            *(float2*)(o1 + 32 + cf) = v;
            v.x = cA[pp][2] * cs.x - cB[pp][2] * sn.x;
            v.y = cA[pp][3] * cs.y - cB[pp][3] * sn.y;
            *(float2*)(o2 + cf) = v;
            v.x = cA[pp][2] * sn.x + cB[pp][2] * cs.x;
            v.y = cA[pp][3] * sn.y + cB[pp][3] * cs.y;
            *(float2*)(o2 + 32 + cf) = v;
        }
    }
}

// ---------------------------------------------------------------------------
extern "C" void kernel_launch(void* const* d_in, const int* in_sizes, int n_in,
                              void* d_out, int out_size) {
    const float* x      = (const float*)d_in[0];
    const float* thetas = (const float*)d_in[1];
    const float* tscale = (const float*)d_in[2];
    const float* rmat   = (const float*)d_in[3];
    const float* invf   = (const float*)d_in[4];
    const int*   pairs  = (const int*)d_in[5];
    float*       out    = (float*)d_out;

    setup_kernel<<<513, 256>>>(thetas, tscale, rmat, pairs, invf);

    int rows   = in_sizes[0] / 64;     // 524288
    int blocks = rows / 128;           // 4096
    cre_hmma_kernel<<<blocks, 128>>>(x, out);
}

// round 8
// speedup vs baseline: 4.0820x; 1.1224x over previous
#include <cuda_runtime.h>
#include <cstdint>

#define S_LEN 4096
#define ROTN  32

// B fragments in per-lane load order, tf32-rounded: [pw][pp][s][lane] ->
// uint4{ M[k0][nA], M[k1][nA], M[k0][nB], M[k1][nB] } with k0=8s+2*tig, k1=k0+1,
// nA=8*(2pw+pp)+g, nB=nA+32, lane=4g+tig.
__device__ uint4  g_Mfrag[2 * 2 * 8 * 32];
// Packed RoPE table: g_sc[spos*16 + j] = {sin[2j], sin[2j+1], cos[2j], cos[2j+1]}
__device__ float4 g_sc[S_LEN * 16];
// Small angle tables (fp64-accurate, stored fp32): [sin/cos][a or b][f]
__device__ float  g_TA[2][64][32];
__device__ float  g_TB[2][64][32];

__device__ __forceinline__ uint32_t f2tf32(float f) {
    uint32_t o;
    asm("cvt.rna.satfinite.tf32.f32 %0, %1;" : "=r"(o) : "f"(f));
    return o;
}
__device__ __forceinline__ uint32_t smem_u32(const void* p) {
    uint32_t a;
    asm("{ .reg .u64 t; cvta.to.shared.u64 t, %1; cvt.u32.u64 %0, t; }"
        : "=r"(a) : "l"(p));
    return a;
}

// ============================ setup stage 1 ================================
// Block 0: M' = B1..B32 * R_perm via reversed row-op scan, then emit g_Mfrag.
// Blocks 1..8: small sin/cos tables (4096 fp64 sincos total).
__global__ void __launch_bounds__(256, 1)
setup1_kernel(const float* __restrict__ thetas,
              const float* __restrict__ theta_scale,
              const float* __restrict__ rmat,
              const int*   __restrict__ pairs,
              const float* __restrict__ inv_freq) {
    const int tid = threadIdx.x;

    if (blockIdx.x != 0) {
        int e = (blockIdx.x - 1) * 256 + tid;   // 0..2047
        int a = e >> 5, f = e & 31;
        double fv = (double)inv_freq[f];
        double sA, cA, sB, cB;
        sincos((double)(64 * a) * fv, &sA, &cA);
        sincos((double)a * fv, &sB, &cB);
        g_TA[0][a][f] = (float)sA;  g_TA[1][a][f] = (float)cA;
        g_TB[0][a][f] = (float)sB;  g_TB[1][a][f] = (float)cB;
        return;
    }

    __shared__ float Ms[64][65];
    __shared__ float AB[ROTN][4];
    __shared__ int   PJ[ROTN][2];

    for (int idx = tid; idx < 64 * 64; idx += 256) {
        int k = idx >> 6, c = idx & 63;
        int pc = (c < 32) ? (2 * c) : (2 * (c - 32) + 1);
        Ms[k][c] = rmat[k * 64 + pc];
    }
    if (tid < ROTN) {
        float th = thetas[tid] * theta_scale[0];
        float c = cosf(th), s = sinf(th);
        AB[tid][0] = (1.0f + 2.0f * c - 2.0f * c * c) * (1.0f / 3.0f);
        AB[tid][1] = (2.0f * s - 2.0f * s * c) * (1.0f / 3.0f);
        AB[tid][2] = -(2.0f * s + 2.0f * c * s) * (1.0f / 3.0f);
        AB[tid][3] = (2.0f * c + 1.0f - 2.0f * s * s) * (1.0f / 3.0f);
        PJ[tid][0] = pairs[2 * tid];
        PJ[tid][1] = pairs[2 * tid + 1];
    }
    __syncthreads();

    if (tid < 64) {
        #pragma unroll
        for (int s = ROTN - 1; s >= 0; --s) {
            int i = PJ[s][0], j = PJ[s][1];
            float a = AB[s][0], b = AB[s][1], gm = AB[s][2], d = AB[s][3];
            float mi = Ms[i][tid], mj = Ms[j][tid];
            Ms[i][tid] = a * mi + gm * mj;
            Ms[j][tid] = b * mi + d * mj;
        }
    }
    __syncthreads();

    // Emit B fragments in per-lane load order, tf32-rounded.
    for (int idx = tid; idx < 2 * 2 * 8 * 32; idx += 256) {
        int lane = idx & 31;
        int s    = (idx >> 5) & 7;
        int pp   = (idx >> 8) & 1;
        int pw   = (idx >> 9) & 1;
        int g = lane >> 2, tig = lane & 3;
        int p  = 2 * pw + pp;
        int nA = 8 * p + g, nB = nA + 32;
        int k0 = 8 * s + 2 * tig, k1 = k0 + 1;
        uint4 q;
        q.x = f2tf32(Ms[k0][nA]);
        q.y = f2tf32(Ms[k1][nA]);
        q.z = f2tf32(Ms[k0][nB]);
        q.w = f2tf32(Ms[k1][nB]);
        g_Mfrag[idx] = q;
    }
}

// ============================ setup stage 2 ================================
// Combine tables: sin(s*f) = sA*cB + cA*sB, cos(s*f) = cA*cB - sA*sB; pack.
__global__ void __launch_bounds__(256, 4)
setup2_kernel() {
    int idx  = blockIdx.x * 256 + threadIdx.x;   // 65536 = 4096*16
    int spos = idx >> 4, j = idx & 15;
    int a = spos >> 6, b = spos & 63;
    int c0 = 2 * j, c1 = 2 * j + 1;
    float sA0 = g_TA[0][a][c0], cA0 = g_TA[1][a][c0];
    float sB0 = g_TB[0][b][c0], cB0 = g_TB[1][b][c0];
    float sA1 = g_TA[0][a][c1], cA1 = g_TA[1][a][c1];
    float sB1 = g_TB[0][b][c1], cB1 = g_TB[1][b][c1];
    float4 r;
    r.x = sA0 * cB0 + cA0 * sB0;   // sin col c0
    r.y = sA1 * cB1 + cA1 * sB1;   // sin col c1
    r.z = cA0 * cB0 - sA0 * sB0;   // cos col c0
    r.w = cA1 * cB1 - sA1 * sB1;   // cos col c1
    g_sc[idx] = r;
}

// ============================ main kernel ==================================
// 128-row tile per CTA, 4 warps. Warp w: n-pairs {2(w&1), 2(w&1)+1}, m-tiles
// {4(w>>1)..+3}. k-permuted frags (pos tig <-> k=8s+2tig) -> LDS.64 A loads.
// B fragments: 16 coalesced LDG.128 from g_Mfrag (pre-tf32).
#define XSTRIDE 72

__device__ __forceinline__ void mma16n8k8(float* c, const uint32_t* a,
                                          uint32_t b0, uint32_t b1) {
    asm volatile(
        "mma.sync.aligned.m16n8k8.row.col.f32.tf32.tf32.f32 "
        "{%0,%1,%2,%3}, {%4,%5,%6,%7}, {%8,%9}, {%0,%1,%2,%3};"
        : "+f"(c[0]), "+f"(c[1]), "+f"(c[2]), "+f"(c[3])
        : "r"(a[0]), "r"(a[1]), "r"(a[2]), "r"(a[3]), "r"(b0), "r"(b1));
}

__global__ void __launch_bounds__(128, 4)
cre_hmma_kernel(const float* __restrict__ x, float* __restrict__ out) {
    __shared__ uint32_t sX[128 * XSTRIDE];   // raw fp32 x tile

    const int tid  = threadIdx.x;
    const int w    = tid >> 5;
    const int lane = tid & 31;
    const int g    = lane >> 2;
    const int tig  = lane & 3;
    const int pw   = w & 1;
    const int mh   = w >> 1;
    const size_t rowBase = (size_t)blockIdx.x * 128;

    // ---- Stage x tile with cp.async ----
    {
        const float4* X4 = (const float4*)(x + rowBase * 64);
        const uint32_t sbase = smem_u32(sX);
        #pragma unroll
        for (int it = 0; it < 16; ++it) {
            int idx4 = tid + 128 * it;
            int r = idx4 >> 4, q = idx4 & 15;
            uint32_t dst = sbase + (uint32_t)(r * XSTRIDE + 4 * q) * 4u;
            asm volatile("cp.async.cg.shared.global [%0], [%1], 16;"
                         :: "r"(dst), "l"(X4 + idx4));
        }
        asm volatile("cp.async.commit_group;" ::: "memory");
    }

    // ---- B fragments: coalesced LDG.128, already tf32 ----
    uint32_t bA[2][8][2], bB[2][8][2];
    #pragma unroll
    for (int pp = 0; pp < 2; ++pp) {
        #pragma unroll
        for (int s = 0; s < 8; ++s) {
            uint4 q = g_Mfrag[(((pw * 2 + pp) * 8) + s) * 32 + lane];
            bA[pp][s][0] = q.x;
            bA[pp][s][1] = q.y;
            bB[pp][s][0] = q.z;
            bB[pp][s][1] = q.w;
        }
    }
    asm volatile("cp.async.wait_group 0;" ::: "memory");
    __syncthreads();

    #pragma unroll
    for (int ml = 0; ml < 4; ++ml) {
        const int mt = 4 * mh + ml;
        float cA[2][4] = {{0.f,0.f,0.f,0.f},{0.f,0.f,0.f,0.f}};
        float cB[2][4] = {{0.f,0.f,0.f,0.f},{0.f,0.f,0.f,0.f}};
        const uint32_t* xlow  = sX + (mt * 16 + g) * XSTRIDE + 2 * tig;
        const uint32_t* xhigh = xlow + 8 * XSTRIDE;

        #pragma unroll
        for (int s = 0; s < 8; ++s) {
            uint2 lo = *(const uint2*)(xlow  + 8 * s);
            uint2 hi = *(const uint2*)(xhigh + 8 * s);
            uint32_t a[4];
            a[0] = f2tf32(__uint_as_float(lo.x));
            a[1] = f2tf32(__uint_as_float(hi.x));
            a[2] = f2tf32(__uint_as_float(lo.y));
            a[3] = f2tf32(__uint_as_float(hi.y));
            #pragma unroll
            for (int pp = 0; pp < 2; ++pp) {
                mma16n8k8(cA[pp], a, bA[pp][s][0], bA[pp][s][1]);
                mma16n8k8(cB[pp], a, bB[pp][s][0], bB[pp][s][1]);
            }
        }

        // ---- RoPE epilogue (packed sin/cos: 1 LDG.128 per pp) ----
        const size_t R0 = rowBase + mt * 16;
        const int spos = (int)((R0 >> 4) & (S_LEN - 1));
        float* o1 = out + (R0 + g) * 64;
        float* o2 = out + (R0 + 8 + g) * 64;

        #pragma unroll
        for (int pp = 0; pp < 2; ++pp) {
            const int p  = 2 * pw + pp;
            const int cf = 8 * p + 2 * tig;
            float4 sc = g_sc[spos * 16 + 4 * p + tig];
            float2 v;
            v.x = cA[pp][0] * sc.z - cB[pp][0] * sc.x;
            v.y = cA[pp][1] * sc.w - cB[pp][1] * sc.y;
            *(float2*)(o1 + cf) = v;
            v.x = cA[pp][0] * sc.x + cB[pp][0] * sc.z;
            v.y = cA[pp][1] * sc.y + cB[pp][1] * sc.w;
            *(float2*)(o1 + 32 + cf) = v;
            v.x = cA[pp][2] * sc.z - cB[pp][2] * sc.x;
            v.y = cA[pp][3] * sc.w - cB[pp][3] * sc.y;
            *(float2*)(o2 + cf) = v;
            v.x = cA[pp][2] * sc.x + cB[pp][2] * sc.z;
            v.y = cA[pp][3] * sc.y + cB[pp][3] * sc.w;
            *(float2*)(o2 + 32 + cf) = v;
        }
    }
}

// ---------------------------------------------------------------------------
extern "C" void kernel_launch(void* const* d_in, const int* in_sizes, int n_in,
                              void* d_out, int out_size) {
    const float* x      = (const float*)d_in[0];
    const float* thetas = (const float*)d_in[1];
    const float* tscale = (const float*)d_in[2];
    const float* rmat   = (const float*)d_in[3];
    const float* invf   = (const float*)d_in[4];
    const int*   pairs  = (const int*)d_in[5];
    float*       out    = (float*)d_out;

    setup1_kernel<<<9, 256>>>(thetas, tscale, rmat, pairs, invf);
    setup2_kernel<<<256, 256>>>();

    int rows   = in_sizes[0] / 64;     // 524288
    int blocks = rows / 128;           // 4096
    cre_hmma_kernel<<<blocks, 128>>>(x, out);
}

// round 9
// speedup vs baseline: 4.0840x; 1.0005x over previous
#include <cuda_runtime.h>
#include <cstdint>

#define S_LEN 4096
#define ROTN  32

// B fragments in per-lane load order, tf32-rounded (see setup1).
__device__ uint4  g_Mfrag[2 * 2 * 8 * 32];
// Packed RoPE table: g_sc[spos*16 + 4p+tig] = {sin c0, sin c1, cos c0, cos c1}
__device__ float4 g_sc[S_LEN * 16];
// Small angle tables (fp64-accurate, stored fp32): [sin/cos][a or b][f]
__device__ float  g_TA[2][64][32];
__device__ float  g_TB[2][64][32];

__device__ __forceinline__ uint32_t f2tf32(float f) {
    uint32_t o;
    asm("cvt.rna.satfinite.tf32.f32 %0, %1;" : "=r"(o) : "f"(f));
    return o;
}
__device__ __forceinline__ uint32_t smem_u32(const void* p) {
    uint32_t a;
    asm("{ .reg .u64 t; cvta.to.shared.u64 t, %1; cvt.u32.u64 %0, t; }"
        : "=r"(a) : "l"(p));
    return a;
}

// ============================ setup stage 1 ================================
// Block 0: M' = B1..B32 * R_perm via reversed row-op scan; emit g_Mfrag.
// Blocks 1..16: small sin/cos tables — ONE fp64 sincos per thread.
__global__ void __launch_bounds__(256, 1)
setup1_kernel(const float* __restrict__ thetas,
              const float* __restrict__ theta_scale,
              const float* __restrict__ rmat,
              const int*   __restrict__ pairs,
              const float* __restrict__ inv_freq) {
    const int tid = threadIdx.x;

    if (blockIdx.x != 0) {
        int e = (blockIdx.x - 1) * 256 + tid;   // 0..4095
        int t = e >> 11;                         // 0 -> TA, 1 -> TB
        int r = e & 2047;
        int a = r >> 5, f = r & 31;
        double fv = (double)inv_freq[f];
        double arg = (t == 0) ? (double)(64 * a) * fv : (double)a * fv;
        double sd, cd;
        sincos(arg, &sd, &cd);
        if (t == 0) { g_TA[0][a][f] = (float)sd; g_TA[1][a][f] = (float)cd; }
        else        { g_TB[0][a][f] = (float)sd; g_TB[1][a][f] = (float)cd; }
        return;
    }

    __shared__ float Ms[64][65];
    __shared__ float AB[ROTN][4];
    __shared__ int   PJ[ROTN][2];

    for (int idx = tid; idx < 64 * 64; idx += 256) {
        int k = idx >> 6, c = idx & 63;
        int pc = (c < 32) ? (2 * c) : (2 * (c - 32) + 1);
        Ms[k][c] = rmat[k * 64 + pc];
    }
    if (tid < ROTN) {
        float th = thetas[tid] * theta_scale[0];
        float c = cosf(th), s = sinf(th);
        AB[tid][0] = (1.0f + 2.0f * c - 2.0f * c * c) * (1.0f / 3.0f);
        AB[tid][1] = (2.0f * s - 2.0f * s * c) * (1.0f / 3.0f);
        AB[tid][2] = -(2.0f * s + 2.0f * c * s) * (1.0f / 3.0f);
        AB[tid][3] = (2.0f * c + 1.0f - 2.0f * s * s) * (1.0f / 3.0f);
        PJ[tid][0] = pairs[2 * tid];
        PJ[tid][1] = pairs[2 * tid + 1];
    }
    __syncthreads();

    if (tid < 64) {
        #pragma unroll
        for (int s = ROTN - 1; s >= 0; --s) {
            int i = PJ[s][0], j = PJ[s][1];
            float a = AB[s][0], b = AB[s][1], gm = AB[s][2], d = AB[s][3];
            float mi = Ms[i][tid], mj = Ms[j][tid];
            Ms[i][tid] = a * mi + gm * mj;
            Ms[j][tid] = b * mi + d * mj;
        }
    }
    __syncthreads();

    for (int idx = tid; idx < 2 * 2 * 8 * 32; idx += 256) {
        int lane = idx & 31;
        int s    = (idx >> 5) & 7;
        int pp   = (idx >> 8) & 1;
        int pw   = (idx >> 9) & 1;
        int g = lane >> 2, tig = lane & 3;
        int p  = 2 * pw + pp;
        int nA = 8 * p + g, nB = nA + 32;
        int k0 = 8 * s + 2 * tig, k1 = k0 + 1;
        uint4 q;
        q.x = f2tf32(Ms[k0][nA]);
        q.y = f2tf32(Ms[k1][nA]);
        q.z = f2tf32(Ms[k0][nB]);
        q.w = f2tf32(Ms[k1][nB]);
        g_Mfrag[idx] = q;
    }
}

// ============================ setup stage 2 ================================
__global__ void __launch_bounds__(256, 4)
setup2_kernel() {
    int idx  = blockIdx.x * 256 + threadIdx.x;   // 65536 = 4096*16
    int spos = idx >> 4, j = idx & 15;
    int a = spos >> 6, b = spos & 63;
    int c0 = 2 * j, c1 = 2 * j + 1;
    float sA0 = g_TA[0][a][c0], cA0 = g_TA[1][a][c0];
    float sB0 = g_TB[0][b][c0], cB0 = g_TB[1][b][c0];
    float sA1 = g_TA[0][a][c1], cA1 = g_TA[1][a][c1];
    float sB1 = g_TB[0][b][c1], cB1 = g_TB[1][b][c1];
    float4 r;
    r.x = sA0 * cB0 + cA0 * sB0;
    r.y = sA1 * cB1 + cA1 * sB1;
    r.z = cA0 * cB0 - sA0 * sB0;
    r.w = cA1 * cB1 - sA1 * sB1;
    g_sc[idx] = r;
}

// ============================ main kernel ==================================
// 128-row tile per CTA, 4 warps. Warp w: n-pairs {2(w&1),2(w&1)+1}, m-tiles
// {4(w>>1)..+3}. LDS.64 A loads via k-permuted frags; B frags via coalesced
// LDG.128. Epilogue: RoPE -> SMEM stage (stride 76, conflict-free STS.64) ->
// cooperative LDS.128 + coalesced STG.128 per half-CTA (named barriers).
#define XSTRIDE 72
#define ESTRIDE 76

__device__ __forceinline__ void mma16n8k8(float* c, const uint32_t* a,
                                          uint32_t b0, uint32_t b1) {
    asm volatile(
        "mma.sync.aligned.m16n8k8.row.col.f32.tf32.tf32.f32 "
        "{%0,%1,%2,%3}, {%4,%5,%6,%7}, {%8,%9}, {%0,%1,%2,%3};"
        : "+f"(c[0]), "+f"(c[1]), "+f"(c[2]), "+f"(c[3])
        : "r"(a[0]), "r"(a[1]), "r"(a[2]), "r"(a[3]), "r"(b0), "r"(b1));
}

__global__ void __launch_bounds__(128, 4)
cre_hmma_kernel(const float* __restrict__ x, float* __restrict__ out) {
    __shared__ uint32_t sX[128 * XSTRIDE];                 // 36864 B
    __shared__ __align__(16) float sEp[2 * 16 * ESTRIDE];  //  9728 B

    const int tid  = threadIdx.x;
    const int w    = tid >> 5;
    const int lane = tid & 31;
    const int g    = lane >> 2;
    const int tig  = lane & 3;
    const int pw   = w & 1;
    const int mh   = w >> 1;           // half id (= tid>>6)
    const int lt   = tid & 63;         // thread id within half
    const size_t rowBase = (size_t)blockIdx.x * 128;

    // ---- Stage x tile with cp.async ----
    {
        const float4* X4 = (const float4*)(x + rowBase * 64);
        const uint32_t sbase = smem_u32(sX);
        #pragma unroll
        for (int it = 0; it < 16; ++it) {
            int idx4 = tid + 128 * it;
            int r = idx4 >> 4, q = idx4 & 15;
            uint32_t dst = sbase + (uint32_t)(r * XSTRIDE + 4 * q) * 4u;
            asm volatile("cp.async.cg.shared.global [%0], [%1], 16;"
                         :: "r"(dst), "l"(X4 + idx4));
        }
        asm volatile("cp.async.commit_group;" ::: "memory");
    }

    // ---- B fragments: coalesced LDG.128, already tf32 ----
    uint32_t bA[2][8][2], bB[2][8][2];
    #pragma unroll
    for (int pp = 0; pp < 2; ++pp) {
        #pragma unroll
        for (int s = 0; s < 8; ++s) {
            uint4 q = g_Mfrag[(((pw * 2 + pp) * 8) + s) * 32 + lane];
            bA[pp][s][0] = q.x;
            bA[pp][s][1] = q.y;
            bB[pp][s][0] = q.z;
            bB[pp][s][1] = q.w;
        }
    }
    asm volatile("cp.async.wait_group 0;" ::: "memory");
    __syncthreads();

    float* ep = sEp + mh * 16 * ESTRIDE;
    const int barid = 1 + mh;

    #pragma unroll
    for (int ml = 0; ml < 4; ++ml) {
        const int mt = 4 * mh + ml;
        float cA[2][4] = {{0.f,0.f,0.f,0.f},{0.f,0.f,0.f,0.f}};
        float cB[2][4] = {{0.f,0.f,0.f,0.f},{0.f,0.f,0.f,0.f}};
        const uint32_t* xlow  = sX + (mt * 16 + g) * XSTRIDE + 2 * tig;
        const uint32_t* xhigh = xlow + 8 * XSTRIDE;

        #pragma unroll
        for (int s = 0; s < 8; ++s) {
            uint2 lo = *(const uint2*)(xlow  + 8 * s);
            uint2 hi = *(const uint2*)(xhigh + 8 * s);
            uint32_t a[4];
            a[0] = f2tf32(__uint_as_float(lo.x));
            a[1] = f2tf32(__uint_as_float(hi.x));
            a[2] = f2tf32(__uint_as_float(lo.y));
            a[3] = f2tf32(__uint_as_float(hi.y));
            #pragma unroll
            for (int pp = 0; pp < 2; ++pp) {
                mma16n8k8(cA[pp], a, bA[pp][s][0], bA[pp][s][1]);
                mma16n8k8(cB[pp], a, bB[pp][s][0], bB[pp][s][1]);
            }
        }

        // ---- RoPE + stage into SMEM (conflict-free STS.64) ----
        const size_t R0 = rowBase + mt * 16;
        const int spos = (int)((R0 >> 4) & (S_LEN - 1));
        #pragma unroll
        for (int pp = 0; pp < 2; ++pp) {
            const int p  = 2 * pw + pp;
            const int cf = 8 * p + 2 * tig;
            float4 sc = g_sc[spos * 16 + 4 * p + tig];
            float2 v;
            v.x = cA[pp][0] * sc.z - cB[pp][0] * sc.x;
            v.y = cA[pp][1] * sc.w - cB[pp][1] * sc.y;
            *(float2*)(ep + g * ESTRIDE + cf) = v;
            v.x = cA[pp][0] * sc.x + cB[pp][0] * sc.z;
            v.y = cA[pp][1] * sc.y + cB[pp][1] * sc.w;
            *(float2*)(ep + g * ESTRIDE + 32 + cf) = v;
            v.x = cA[pp][2] * sc.z - cB[pp][2] * sc.x;
            v.y = cA[pp][3] * sc.w - cB[pp][3] * sc.y;
            *(float2*)(ep + (g + 8) * ESTRIDE + cf) = v;
            v.x = cA[pp][2] * sc.x + cB[pp][2] * sc.z;
            v.y = cA[pp][3] * sc.y + cB[pp][3] * sc.w;
            *(float2*)(ep + (g + 8) * ESTRIDE + 32 + cf) = v;
        }

        asm volatile("bar.sync %0, 64;" :: "r"(barid) : "memory");

        // ---- Cooperative coalesced store: 16 rows x 256 B ----
        float4* o4 = (float4*)(out + R0 * 64);
        #pragma unroll
        for (int j = 0; j < 4; ++j) {
            int c = j * 64 + lt;             // 0..255
            int r = c >> 4, c16 = c & 15;
            float4 v = *(const float4*)(ep + r * ESTRIDE + c16 * 4);
            o4[c] = v;
        }

        asm volatile("bar.sync %0, 64;" :: "r"(barid) : "memory");
    }
}

// ---------------------------------------------------------------------------
extern "C" void kernel_launch(void* const* d_in, const int* in_sizes, int n_in,
                              void* d_out, int out_size) {
    const float* x      = (const float*)d_in[0];
    const float* thetas = (const float*)d_in[1];
    const float* tscale = (const float*)d_in[2];
    const float* rmat   = (const float*)d_in[3];
    const float* invf   = (const float*)d_in[4];
    const int*   pairs  = (const int*)d_in[5];
    float*       out    = (float*)d_out;

    setup1_kernel<<<17, 256>>>(thetas, tscale, rmat, pairs, invf);
    setup2_kernel<<<256, 256>>>();

    int rows   = in_sizes[0] / 64;     // 524288
    int blocks = rows / 128;           // 4096
    cre_hmma_kernel<<<blocks, 128>>>(x, out);
}

// round 10
// speedup vs baseline: 4.2212x; 1.0336x over previous
#include <cuda_runtime.h>
#include <cstdint>

#define S_LEN 4096
#define ROTN  32

// B fragments in per-lane load order, tf32-rounded (see setup).
__device__ uint4  g_Mfrag[2 * 2 * 8 * 32];
// Packed RoPE table: g_sc[spos*16 + 4p+tig] = {sin c0, sin c1, cos c0, cos c1}
__device__ float4 g_sc[S_LEN * 16];

__device__ __forceinline__ uint32_t f2tf32(float f) {
    uint32_t o;
    asm("cvt.rna.satfinite.tf32.f32 %0, %1;" : "=r"(o) : "f"(f));
    return o;
}
__device__ __forceinline__ uint32_t smem_u32(const void* p) {
    uint32_t a;
    asm("{ .reg .u64 t; cvta.to.shared.u64 t, %1; cvt.u32.u64 %0, t; }"
        : "=r"(a) : "l"(p));
    return a;
}

// Accurate fp32 sincos for x in [0, ~4100] (immune to --use_fast_math).
// Cody-Waite 3-part reduction (exact via fmaf; n <= 2608 here) + fdlibm polys.
// Abs error ~1-2 ulp — far inside the 1e-3 tolerance next to tf32's 3e-4.
__device__ __forceinline__ float2 acc_sincos(float x) {
    float n = rintf(x * 0.636619772367581343f);
    float r = fmaf(n, -1.57079625129699707031e+00f, x);
    r = fmaf(n, -7.54978941586159635335e-08f, r);
    r = fmaf(n, -5.39030252995776476554e-15f, r);
    int q = (int)n & 3;
    float r2 = r * r;
    float ps = -1.9515296e-4f;
    ps = fmaf(ps, r2, 8.3321608e-3f);
    ps = fmaf(ps, r2, -1.6666654e-1f);
    float sr = fmaf(ps * r2, r, r);
    float pc = 2.4433157e-5f;
    pc = fmaf(pc, r2, -1.3887316e-3f);
    pc = fmaf(pc, r2, 4.1666646e-2f);
    pc = fmaf(pc, r2, -4.9999997e-1f);
    float cr = fmaf(pc, r2, 1.0f);
    float2 o;
    if (q == 0)      { o.x = sr;  o.y = cr;  }
    else if (q == 1) { o.x = cr;  o.y = -sr; }
    else if (q == 2) { o.x = -sr; o.y = -cr; }
    else             { o.x = -cr; o.y = sr;  }
    return o;   // {sin, cos}
}

// ============================ setup kernel =================================
// Block 0: M' = B1..B32 * R_perm via reversed row-op scan; emit g_Mfrag.
// Blocks 1..256: full g_sc table via fp32 Cody-Waite sincos (no fp64 at all).
__global__ void __launch_bounds__(256, 1)
setup_kernel(const float* __restrict__ thetas,
             const float* __restrict__ theta_scale,
             const float* __restrict__ rmat,
             const int*   __restrict__ pairs,
             const float* __restrict__ inv_freq) {
    const int tid = threadIdx.x;

    if (blockIdx.x != 0) {
        int idx  = (blockIdx.x - 1) * 256 + tid;   // 0..65535 = S_LEN*16
        int spos = idx >> 4, j = idx & 15;
        float f0 = inv_freq[2 * j];
        float f1 = inv_freq[2 * j + 1];
        float2 sc0 = acc_sincos((float)spos * f0);
        float2 sc1 = acc_sincos((float)spos * f1);
        float4 r;
        r.x = sc0.x;   // sin c0
        r.y = sc1.x;   // sin c1
        r.z = sc0.y;   // cos c0
        r.w = sc1.y;   // cos c1
        g_sc[idx] = r;
        return;
    }

    __shared__ float Ms[64][65];
    __shared__ float AB[ROTN][4];
    __shared__ int   PJ[ROTN][2];

    for (int idx = tid; idx < 64 * 64; idx += 256) {
        int k = idx >> 6, c = idx & 63;
        int pc = (c < 32) ? (2 * c) : (2 * (c - 32) + 1);
        Ms[k][c] = rmat[k * 64 + pc];
    }
    if (tid < ROTN) {
        float th = thetas[tid] * theta_scale[0];
        float c = cosf(th), s = sinf(th);   // |th| small: fast-math fine
        AB[tid][0] = (1.0f + 2.0f * c - 2.0f * c * c) * (1.0f / 3.0f);
        AB[tid][1] = (2.0f * s - 2.0f * s * c) * (1.0f / 3.0f);
        AB[tid][2] = -(2.0f * s + 2.0f * c * s) * (1.0f / 3.0f);
        AB[tid][3] = (2.0f * c + 1.0f - 2.0f * s * s) * (1.0f / 3.0f);
        PJ[tid][0] = pairs[2 * tid];
        PJ[tid][1] = pairs[2 * tid + 1];
    }
    __syncthreads();

    if (tid < 64) {
        #pragma unroll
        for (int s = ROTN - 1; s >= 0; --s) {
            int i = PJ[s][0], j = PJ[s][1];
            float a = AB[s][0], b = AB[s][1], gm = AB[s][2], d = AB[s][3];
            float mi = Ms[i][tid], mj = Ms[j][tid];
            Ms[i][tid] = a * mi + gm * mj;
            Ms[j][tid] = b * mi + d * mj;
        }
    }
    __syncthreads();

    for (int idx = tid; idx < 2 * 2 * 8 * 32; idx += 256) {
        int lane = idx & 31;
        int s    = (idx >> 5) & 7;
        int pp   = (idx >> 8) & 1;
        int pw   = (idx >> 9) & 1;
        int g = lane >> 2, tig = lane & 3;
        int p  = 2 * pw + pp;
        int nA = 8 * p + g, nB = nA + 32;
        int k0 = 8 * s + 2 * tig, k1 = k0 + 1;
        uint4 q;
        q.x = f2tf32(Ms[k0][nA]);
        q.y = f2tf32(Ms[k1][nA]);
        q.z = f2tf32(Ms[k0][nB]);
        q.w = f2tf32(Ms[k1][nB]);
        g_Mfrag[idx] = q;
    }
}

// ============================ main kernel ==================================
// 128-row tile per CTA, 4 warps. Warp w: n-pairs {2(w&1),2(w&1)+1}, m-tiles
// {4(w>>1)..+3}. LDS.64 A loads via k-permuted frags; B frags via coalesced
// LDG.128. Epilogue: RoPE -> SMEM stage -> coalesced STG.128 per half-CTA.
#define XSTRIDE 72
#define ESTRIDE 76

__device__ __forceinline__ void mma16n8k8(float* c, const uint32_t* a,
                                          uint32_t b0, uint32_t b1) {
    asm volatile(
        "mma.sync.aligned.m16n8k8.row.col.f32.tf32.tf32.f32 "
        "{%0,%1,%2,%3}, {%4,%5,%6,%7}, {%8,%9}, {%0,%1,%2,%3};"
        : "+f"(c[0]), "+f"(c[1]), "+f"(c[2]), "+f"(c[3])
        : "r"(a[0]), "r"(a[1]), "r"(a[2]), "r"(a[3]), "r"(b0), "r"(b1));
}

__global__ void __launch_bounds__(128, 4)
cre_hmma_kernel(const float* __restrict__ x, float* __restrict__ out) {
    __shared__ uint32_t sX[128 * XSTRIDE];
    __shared__ __align__(16) float sEp[2 * 16 * ESTRIDE];

    const int tid  = threadIdx.x;
    const int w    = tid >> 5;
    const int lane = tid & 31;
    const int g    = lane >> 2;
    const int tig  = lane & 3;
    const int pw   = w & 1;
    const int mh   = w >> 1;
    const int lt   = tid & 63;
    const size_t rowBase = (size_t)blockIdx.x * 128;

    {
        const float4* X4 = (const float4*)(x + rowBase * 64);
        const uint32_t sbase = smem_u32(sX);
        #pragma unroll
        for (int it = 0; it < 16; ++it) {
            int idx4 = tid + 128 * it;
            int r = idx4 >> 4, q = idx4 & 15;
            uint32_t dst = sbase + (uint32_t)(r * XSTRIDE + 4 * q) * 4u;
            asm volatile("cp.async.cg.shared.global [%0], [%1], 16;"
                         :: "r"(dst), "l"(X4 + idx4));
        }
        asm volatile("cp.async.commit_group;" ::: "memory");
    }

    uint32_t bA[2][8][2], bB[2][8][2];
    #pragma unroll
    for (int pp = 0; pp < 2; ++pp) {
        #pragma unroll
        for (int s = 0; s < 8; ++s) {
            uint4 q = g_Mfrag[(((pw * 2 + pp) * 8) + s) * 32 + lane];
            bA[pp][s][0] = q.x;
            bA[pp][s][1] = q.y;
            bB[pp][s][0] = q.z;
            bB[pp][s][1] = q.w;
        }
    }
    asm volatile("cp.async.wait_group 0;" ::: "memory");
    __syncthreads();

    float* ep = sEp + mh * 16 * ESTRIDE;
    const int barid = 1 + mh;

    #pragma unroll
    for (int ml = 0; ml < 4; ++ml) {
        const int mt = 4 * mh + ml;
        float cA[2][4] = {{0.f,0.f,0.f,0.f},{0.f,0.f,0.f,0.f}};
        float cB[2][4] = {{0.f,0.f,0.f,0.f},{0.f,0.f,0.f,0.f}};
        const uint32_t* xlow  = sX + (mt * 16 + g) * XSTRIDE + 2 * tig;
        const uint32_t* xhigh = xlow + 8 * XSTRIDE;

        #pragma unroll
        for (int s = 0; s < 8; ++s) {
            uint2 lo = *(const uint2*)(xlow  + 8 * s);
            uint2 hi = *(const uint2*)(xhigh + 8 * s);
            uint32_t a[4];
            a[0] = f2tf32(__uint_as_float(lo.x));
            a[1] = f2tf32(__uint_as_float(hi.x));
            a[2] = f2tf32(__uint_as_float(lo.y));
            a[3] = f2tf32(__uint_as_float(hi.y));
            #pragma unroll
            for (int pp = 0; pp < 2; ++pp) {
                mma16n8k8(cA[pp], a, bA[pp][s][0], bA[pp][s][1]);
                mma16n8k8(cB[pp], a, bB[pp][s][0], bB[pp][s][1]);
            }
        }

        const size_t R0 = rowBase + mt * 16;
        const int spos = (int)((R0 >> 4) & (S_LEN - 1));
        #pragma unroll
        for (int pp = 0; pp < 2; ++pp) {
            const int p  = 2 * pw + pp;
            const int cf = 8 * p + 2 * tig;
            float4 sc = g_sc[spos * 16 + 4 * p + tig];
            float2 v;
            v.x = cA[pp][0] * sc.z - cB[pp][0] * sc.x;
            v.y = cA[pp][1] * sc.w - cB[pp][1] * sc.y;
            *(float2*)(ep + g * ESTRIDE + cf) = v;
            v.x = cA[pp][0] * sc.x + cB[pp][0] * sc.z;
            v.y = cA[pp][1] * sc.y + cB[pp][1] * sc.w;
            *(float2*)(ep + g * ESTRIDE + 32 + cf) = v;
            v.x = cA[pp][2] * sc.z - cB[pp][2] * sc.x;
            v.y = cA[pp][3] * sc.w - cB[pp][3] * sc.y;
            *(float2*)(ep + (g + 8) * ESTRIDE + cf) = v;
            v.x = cA[pp][2] * sc.x + cB[pp][2] * sc.z;
            v.y = cA[pp][3] * sc.y + cB[pp][3] * sc.w;
            *(float2*)(ep + (g + 8) * ESTRIDE + 32 + cf) = v;
        }

        asm volatile("bar.sync %0, 64;" :: "r"(barid) : "memory");

        float4* o4 = (float4*)(out + R0 * 64);
        #pragma unroll
        for (int j = 0; j < 4; ++j) {
            int c = j * 64 + lt;
            int r = c >> 4, c16 = c & 15;
            float4 v = *(const float4*)(ep + r * ESTRIDE + c16 * 4);
            o4[c] = v;
        }

        asm volatile("bar.sync %0, 64;" :: "r"(barid) : "memory");
    }
}

// ---------------------------------------------------------------------------
extern "C" void kernel_launch(void* const* d_in, const int* in_sizes, int n_in,
                              void* d_out, int out_size) {
    const float* x      = (const float*)d_in[0];
    const float* thetas = (const float*)d_in[1];
    const float* tscale = (const float*)d_in[2];
    const float* rmat   = (const float*)d_in[3];
    const float* invf   = (const float*)d_in[4];
    const int*   pairs  = (const int*)d_in[5];
    float*       out    = (float*)d_out;

    setup_kernel<<<257, 256>>>(thetas, tscale, rmat, pairs, invf);

    int rows   = in_sizes[0] / 64;     // 524288
    int blocks = rows / 128;           // 4096
    cre_hmma_kernel<<<blocks, 128>>>(x, out);
}

// round 11
// speedup vs baseline: 4.5479x; 1.0774x over previous
#include <cuda_runtime.h>
#include <cstdint>

#define S_LEN 4096
#define ROTN  32

// B fragments in per-lane load order, tf32-rounded (see scan_kernel).
__device__ uint4  g_Mfrag[2 * 2 * 8 * 32];
// Packed RoPE table: g_sc[spos*16 + 4p+tig] = {sin c0, sin c1, cos c0, cos c1}
__device__ float4 g_sc[S_LEN * 16];

__device__ __forceinline__ uint32_t f2tf32(float f) {
    uint32_t o;
    asm("cvt.rna.satfinite.tf32.f32 %0, %1;" : "=r"(o) : "f"(f));
    return o;
}
__device__ __forceinline__ uint32_t smem_u32(const void* p) {
    uint32_t a;
    asm("{ .reg .u64 t; cvta.to.shared.u64 t, %1; cvt.u32.u64 %0, t; }"
        : "=r"(a) : "l"(p));
    return a;
}

// Accurate fp32 sincos for x in [0, ~4100] (immune to --use_fast_math).
__device__ __forceinline__ float2 acc_sincos(float x) {
    float n = rintf(x * 0.636619772367581343f);
    float r = fmaf(n, -1.57079625129699707031e+00f, x);
    r = fmaf(n, -7.54978941586159635335e-08f, r);
    r = fmaf(n, -5.39030252995776476554e-15f, r);
    int q = (int)n & 3;
    float r2 = r * r;
    float ps = -1.9515296e-4f;
    ps = fmaf(ps, r2, 8.3321608e-3f);
    ps = fmaf(ps, r2, -1.6666654e-1f);
    float sr = fmaf(ps * r2, r, r);
    float pc = 2.4433157e-5f;
    pc = fmaf(pc, r2, -1.3887316e-3f);
    pc = fmaf(pc, r2, 4.1666646e-2f);
    pc = fmaf(pc, r2, -4.9999997e-1f);
    float cr = fmaf(pc, r2, 1.0f);
    float2 o;
    if (q == 0)      { o.x = sr;  o.y = cr;  }
    else if (q == 1) { o.x = cr;  o.y = -sr; }
    else if (q == 2) { o.x = -sr; o.y = -cr; }
    else             { o.x = -cr; o.y = sr;  }
    return o;
}

// ============================ scan kernel ==================================
// One block: M' = B1..B32 * R_perm via reversed row-op scan; emit g_Mfrag.
// All bulk loops explicitly unrolled so the LDGs batch (high MLP), and the
// small pairs/thetas loads issue FIRST to overlap the rmat staging latency.
__global__ void __launch_bounds__(256, 1)
scan_kernel(const float* __restrict__ thetas,
            const float* __restrict__ theta_scale,
            const float* __restrict__ rmat,
            const int*   __restrict__ pairs) {
    __shared__ float Ms[64][65];
    __shared__ float AB[ROTN][4];
    __shared__ int   PJ[ROTN][2];
    const int tid = threadIdx.x;

    // Small loads first (latency overlaps the staging below).
    float th_v = 0.f, ts_v = 0.f;
    int pi = 0, pj = 0;
    if (tid < ROTN) {
        th_v = thetas[tid];
        ts_v = theta_scale[0];
        pi = pairs[2 * tid];
        pj = pairs[2 * tid + 1];
    }

    // Stage R_perm: 16 independent LDG+STS per thread, fully unrolled.
    #pragma unroll
    for (int it = 0; it < 16; ++it) {
        int idx = tid + 256 * it;
        int k = idx >> 6, c = idx & 63;
        int pc = (c < 32) ? (2 * c) : (2 * (c - 32) + 1);
        Ms[k][c] = rmat[k * 64 + pc];
    }

    if (tid < ROTN) {
        float th = th_v * ts_v;
        float c = cosf(th), s = sinf(th);   // |th| small: fast-math fine
        AB[tid][0] = (1.0f + 2.0f * c - 2.0f * c * c) * (1.0f / 3.0f);
        AB[tid][1] = (2.0f * s - 2.0f * s * c) * (1.0f / 3.0f);
        AB[tid][2] = -(2.0f * s + 2.0f * c * s) * (1.0f / 3.0f);
        AB[tid][3] = (2.0f * c + 1.0f - 2.0f * s * s) * (1.0f / 3.0f);
        PJ[tid][0] = pi;
        PJ[tid][1] = pj;
    }
    __syncthreads();

    // Reversed scan: thread t < 64 owns column t (independent, no syncs).
    if (tid < 64) {
        #pragma unroll
        for (int s = ROTN - 1; s >= 0; --s) {
            int i = PJ[s][0], j = PJ[s][1];
            float a = AB[s][0], b = AB[s][1], gm = AB[s][2], d = AB[s][3];
            float mi = Ms[i][tid], mj = Ms[j][tid];
            Ms[i][tid] = a * mi + gm * mj;
            Ms[j][tid] = b * mi + d * mj;
        }
    }
    __syncthreads();

    // Emit B fragments in per-lane load order, tf32-rounded (4 its, unrolled).
    #pragma unroll
    for (int it = 0; it < 4; ++it) {
        int idx = tid + 256 * it;
        int lane = idx & 31;
        int s    = (idx >> 5) & 7;
        int pp   = (idx >> 8) & 1;
        int pw   = (idx >> 9) & 1;
        int g = lane >> 2, tig = lane & 3;
        int p  = 2 * pw + pp;
        int nA = 8 * p + g, nB = nA + 32;
        int k0 = 8 * s + 2 * tig, k1 = k0 + 1;
        uint4 q;
        q.x = f2tf32(Ms[k0][nA]);
        q.y = f2tf32(Ms[k1][nA]);
        q.z = f2tf32(Ms[k0][nB]);
        q.w = f2tf32(Ms[k1][nB]);
        g_Mfrag[idx] = q;
    }
}

// ============================ table kernel =================================
__global__ void __launch_bounds__(256, 4)
table_kernel(const float* __restrict__ inv_freq) {
    int idx  = blockIdx.x * 256 + threadIdx.x;   // 65536 = S_LEN*16
    int spos = idx >> 4, j = idx & 15;
    float f0 = inv_freq[2 * j];
    float f1 = inv_freq[2 * j + 1];
    float2 sc0 = acc_sincos((float)spos * f0);
    float2 sc1 = acc_sincos((float)spos * f1);
    float4 r;
    r.x = sc0.x;
    r.y = sc1.x;
    r.z = sc0.y;
    r.w = sc1.y;
    g_sc[idx] = r;
}

// ============================ main kernel ==================================
// (unchanged from R10 — 47.2us, near its 4-CTA DRAM ceiling)
#define XSTRIDE 72
#define ESTRIDE 76

__device__ __forceinline__ void mma16n8k8(float* c, const uint32_t* a,
                                          uint32_t b0, uint32_t b1) {
    asm volatile(
        "mma.sync.aligned.m16n8k8.row.col.f32.tf32.tf32.f32 "
        "{%0,%1,%2,%3}, {%4,%5,%6,%7}, {%8,%9}, {%0,%1,%2,%3};"
        : "+f"(c[0]), "+f"(c[1]), "+f"(c[2]), "+f"(c[3])
        : "r"(a[0]), "r"(a[1]), "r"(a[2]), "r"(a[3]), "r"(b0), "r"(b1));
}

__global__ void __launch_bounds__(128, 4)
cre_hmma_kernel(const float* __restrict__ x, float* __restrict__ out) {
    __shared__ uint32_t sX[128 * XSTRIDE];
    __shared__ __align__(16) float sEp[2 * 16 * ESTRIDE];

    const int tid  = threadIdx.x;
    const int w    = tid >> 5;
    const int lane = tid & 31;
    const int g    = lane >> 2;
    const int tig  = lane & 3;
    const int pw   = w & 1;
    const int mh   = w >> 1;
    const int lt   = tid & 63;
    const size_t rowBase = (size_t)blockIdx.x * 128;

    {
        const float4* X4 = (const float4*)(x + rowBase * 64);
        const uint32_t sbase = smem_u32(sX);
        #pragma unroll
        for (int it = 0; it < 16; ++it) {
            int idx4 = tid + 128 * it;
            int r = idx4 >> 4, q = idx4 & 15;
            uint32_t dst = sbase + (uint32_t)(r * XSTRIDE + 4 * q) * 4u;
            asm volatile("cp.async.cg.shared.global [%0], [%1], 16;"
                         :: "r"(dst), "l"(X4 + idx4));
        }
        asm volatile("cp.async.commit_group;" ::: "memory");
    }

    uint32_t bA[2][8][2], bB[2][8][2];
    #pragma unroll
    for (int pp = 0; pp < 2; ++pp) {
        #pragma unroll
        for (int s = 0; s < 8; ++s) {
            uint4 q = g_Mfrag[(((pw * 2 + pp) * 8) + s) * 32 + lane];
            bA[pp][s][0] = q.x;
            bA[pp][s][1] = q.y;
            bB[pp][s][0] = q.z;
            bB[pp][s][1] = q.w;
        }
    }
    asm volatile("cp.async.wait_group 0;" ::: "memory");
    __syncthreads();

    float* ep = sEp + mh * 16 * ESTRIDE;
    const int barid = 1 + mh;

    #pragma unroll
    for (int ml = 0; ml < 4; ++ml) {
        const int mt = 4 * mh + ml;
        float cA[2][4] = {{0.f,0.f,0.f,0.f},{0.f,0.f,0.f,0.f}};
        float cB[2][4] = {{0.f,0.f,0.f,0.f},{0.f,0.f,0.f,0.f}};
        const uint32_t* xlow  = sX + (mt * 16 + g) * XSTRIDE + 2 * tig;
        const uint32_t* xhigh = xlow + 8 * XSTRIDE;

        #pragma unroll
        for (int s = 0; s < 8; ++s) {
            uint2 lo = *(const uint2*)(xlow  + 8 * s);
            uint2 hi = *(const uint2*)(xhigh + 8 * s);
            uint32_t a[4];
            a[0] = f2tf32(__uint_as_float(lo.x));
            a[1] = f2tf32(__uint_as_float(hi.x));
            a[2] = f2tf32(__uint_as_float(lo.y));
            a[3] = f2tf32(__uint_as_float(hi.y));
            #pragma unroll
            for (int pp = 0; pp < 2; ++pp) {
                mma16n8k8(cA[pp], a, bA[pp][s][0], bA[pp][s][1]);
                mma16n8k8(cB[pp], a, bB[pp][s][0], bB[pp][s][1]);
            }
        }

        const size_t R0 = rowBase + mt * 16;
        const int spos = (int)((R0 >> 4) & (S_LEN - 1));
        #pragma unroll
        for (int pp = 0; pp < 2; ++pp) {
            const int p  = 2 * pw + pp;
            const int cf = 8 * p + 2 * tig;
            float4 sc = g_sc[spos * 16 + 4 * p + tig];
            float2 v;
            v.x = cA[pp][0] * sc.z - cB[pp][0] * sc.x;
            v.y = cA[pp][1] * sc.w - cB[pp][1] * sc.y;
            *(float2*)(ep + g * ESTRIDE + cf) = v;
            v.x = cA[pp][0] * sc.x + cB[pp][0] * sc.z;
            v.y = cA[pp][1] * sc.y + cB[pp][1] * sc.w;
            *(float2*)(ep + g * ESTRIDE + 32 + cf) = v;
            v.x = cA[pp][2] * sc.z - cB[pp][2] * sc.x;
            v.y = cA[pp][3] * sc.w - cB[pp][3] * sc.y;
            *(float2*)(ep + (g + 8) * ESTRIDE + cf) = v;
            v.x = cA[pp][2] * sc.x + cB[pp][2] * sc.z;
            v.y = cA[pp][3] * sc.y + cB[pp][3] * sc.w;
            *(float2*)(ep + (g + 8) * ESTRIDE + 32 + cf) = v;
        }

        asm volatile("bar.sync %0, 64;" :: "r"(barid) : "memory");

        float4* o4 = (float4*)(out + R0 * 64);
        #pragma unroll
        for (int j = 0; j < 4; ++j) {
            int c = j * 64 + lt;
            int r = c >> 4, c16 = c & 15;
            float4 v = *(const float4*)(ep + r * ESTRIDE + c16 * 4);
            o4[c] = v;
        }

        asm volatile("bar.sync %0, 64;" :: "r"(barid) : "memory");
    }
}

// ---------------------------------------------------------------------------
extern "C" void kernel_launch(void* const* d_in, const int* in_sizes, int n_in,
                              void* d_out, int out_size) {
    const float* x      = (const float*)d_in[0];
    const float* thetas = (const float*)d_in[1];
    const float* tscale = (const float*)d_in[2];
    const float* rmat   = (const float*)d_in[3];
    const float* invf   = (const float*)d_in[4];
    const int*   pairs  = (const int*)d_in[5];
    float*       out    = (float*)d_out;

    scan_kernel<<<1, 256>>>(thetas, tscale, rmat, pairs);
    table_kernel<<<256, 256>>>(invf);

    int rows   = in_sizes[0] / 64;     // 524288
    int blocks = rows / 128;           // 4096
    cre_hmma_kernel<<<blocks, 128>>>(x, out);
}